// round 1
// baseline (speedup 1.0000x reference)
#include <cuda_runtime.h>

#define BB 4
#define SS 1024
#define DIM 2048
#define NH 32
#define NKV 8
#define HD 64
#define QPK 4          // Q heads per KV head
#define ASH 3072       // (NH + 2*NKV) * HD
#define HHALF 32       // HD/2

// Scratch (device globals — allocation-free per harness rules)
__device__ float g_qkv[BB * SS * ASH];   // fused qkv projection output
__device__ float g_o[BB * SS * DIM];     // attention output (b,s,h*HD+d)

// ---------------------------------------------------------------------------
// SGEMM: C[M,N] = A[M,K] * B[N,K]^T   (A row-major MxK, Bm row-major NxK)
// 64x64 tile, BK=16, 256 threads, 4x4 micro-tile per thread.
// M,N multiples of 64; K multiple of 16 (true for all our shapes).
// ---------------------------------------------------------------------------
__global__ __launch_bounds__(256) void sgemm_nt(
    const float* __restrict__ A, const float* __restrict__ Bm,
    float* __restrict__ C, int M, int N, int K)
{
    __shared__ float As[16][65];
    __shared__ float Bs[16][65];

    const int t  = threadIdx.x;
    const int tx = t % 16;        // N direction
    const int ty = t / 16;        // M direction
    const int m0 = blockIdx.y * 64;
    const int n0 = blockIdx.x * 64;

    const int lr = t / 4;         // 0..63 : row within tile for loads
    const int lc = (t % 4) * 4;   // 0,4,8,12 : k-col start for loads

    float acc[4][4];
#pragma unroll
    for (int i = 0; i < 4; i++)
#pragma unroll
        for (int j = 0; j < 4; j++) acc[i][j] = 0.f;

    for (int k0 = 0; k0 < K; k0 += 16) {
        float4 av = *(const float4*)(A  + (size_t)(m0 + lr) * K + k0 + lc);
        float4 bv = *(const float4*)(Bm + (size_t)(n0 + lr) * K + k0 + lc);
        As[lc + 0][lr] = av.x; As[lc + 1][lr] = av.y;
        As[lc + 2][lr] = av.z; As[lc + 3][lr] = av.w;
        Bs[lc + 0][lr] = bv.x; Bs[lc + 1][lr] = bv.y;
        Bs[lc + 2][lr] = bv.z; Bs[lc + 3][lr] = bv.w;
        __syncthreads();

#pragma unroll
        for (int k = 0; k < 16; ++k) {
            float a[4], b[4];
#pragma unroll
            for (int i = 0; i < 4; i++) a[i] = As[k][ty * 4 + i];
#pragma unroll
            for (int j = 0; j < 4; j++) b[j] = Bs[k][tx * 4 + j];
#pragma unroll
            for (int i = 0; i < 4; i++)
#pragma unroll
                for (int j = 0; j < 4; j++) acc[i][j] = fmaf(a[i], b[j], acc[i][j]);
        }
        __syncthreads();
    }

#pragma unroll
    for (int i = 0; i < 4; i++) {
        float* crow = C + (size_t)(m0 + ty * 4 + i) * N + n0 + tx * 4;
#pragma unroll
        for (int j = 0; j < 4; j++) crow[j] = acc[i][j];
    }
}

// ---------------------------------------------------------------------------
// RoPE on Q (32 heads) and K (8 heads), interleaved (real, imag) pairs.
// One thread per pair.
// ---------------------------------------------------------------------------
__global__ void rope_kernel(const float* __restrict__ cosf,
                            const float* __restrict__ sinf)
{
    const int total = BB * SS * (NH + NKV) * HHALF;
    int idx = blockIdx.x * blockDim.x + threadIdx.x;
    if (idx >= total) return;

    int pair = idx % HHALF;
    int tmp  = idx / HHALF;
    int h    = tmp % (NH + NKV);
    tmp     /= (NH + NKV);
    int s    = tmp % SS;
    int b    = tmp / SS;

    int a;
    if (h < NH) a = (h / QPK) * ((QPK + 2) * HD) + (h % QPK) * HD;   // q head
    else        a = (h - NH) * ((QPK + 2) * HD) + QPK * HD;          // k head

    float* p = g_qkv + (size_t)(b * SS + s) * ASH + a + 2 * pair;
    float c  = cosf[s * HHALF + pair];
    float sn = sinf[s * HHALF + pair];
    float xr = p[0], xi = p[1];
    p[0] = xr * c - xi * sn;
    p[1] = xr * sn + xi * c;
}

// ---------------------------------------------------------------------------
// Causal flash attention, fp32. BM=BN=64, HD=64.
// 64 threads/block; thread r owns query row r of the tile (q + o in regs).
// Scores staged in smem as Ss[j][r] (conflict-free across lanes).
// Grid: (S/64, NH, B).
// ---------------------------------------------------------------------------
__global__ __launch_bounds__(64) void flash_kernel()
{
    __shared__ float Ks[64][64];
    __shared__ float Vs[64][64];
    __shared__ float Ss[64][64];   // [j][r]

    const int r  = threadIdx.x;
    const int qb = blockIdx.x;
    const int h  = blockIdx.y;
    const int b  = blockIdx.z;

    const int kv   = h / QPK;
    const int qoff = kv * 384 + (h % QPK) * 64;
    const int koff = kv * 384 + 256;
    const int voff = kv * 384 + 320;
    const int qrow = qb * 64 + r;

    const float* qptr = g_qkv + (size_t)(b * SS + qrow) * ASH + qoff;
    float4 q[16];
#pragma unroll
    for (int i = 0; i < 16; i++) q[i] = ((const float4*)qptr)[i];

    float o[64];
#pragma unroll
    for (int d = 0; d < 64; d++) o[d] = 0.f;
    float m = -1e30f, l = 0.f;
    const float scale = 0.125f;    // 1/sqrt(64)

    for (int kb = 0; kb <= qb; ++kb) {
        const float* kbase = g_qkv + (size_t)(b * SS + kb * 64) * ASH;
        // cooperative tile load: 64 threads x 16 float4 each
#pragma unroll
        for (int it = 0; it < 16; ++it) {
            int f   = r + it * 64;         // 0..1023 float4 index
            int row = f >> 4;
            int c4  = f & 15;
            ((float4*)Ks)[row * 16 + c4] =
                *(const float4*)(kbase + (size_t)row * ASH + koff + c4 * 4);
            ((float4*)Vs)[row * 16 + c4] =
                *(const float4*)(kbase + (size_t)row * ASH + voff + c4 * 4);
        }
        __syncthreads();

        // pass 1: scores + tile max
        float tmax = -1e30f;
        for (int j = 0; j < 64; ++j) {
            const float4* kj = (const float4*)Ks[j];
            float s_ = 0.f;
#pragma unroll
            for (int i = 0; i < 16; i++) {
                float4 kk = kj[i];
                s_ = fmaf(q[i].x, kk.x, s_);
                s_ = fmaf(q[i].y, kk.y, s_);
                s_ = fmaf(q[i].z, kk.z, s_);
                s_ = fmaf(q[i].w, kk.w, s_);
            }
            int kcol = kb * 64 + j;
            s_ = (kcol <= qrow) ? s_ * scale : -1e30f;
            Ss[j][r] = s_;
            tmax = fmaxf(tmax, s_);
        }

        float mnew  = fmaxf(m, tmax);
        float alpha = __expf(m - mnew);
        l *= alpha;
#pragma unroll
        for (int d = 0; d < 64; d++) o[d] *= alpha;

        // pass 2: exp + P@V
        for (int j = 0; j < 64; ++j) {
            float p = __expf(Ss[j][r] - mnew);
            l += p;
            const float4* vj = (const float4*)Vs[j];
#pragma unroll
            for (int i = 0; i < 16; i++) {
                float4 vv = vj[i];
                o[4 * i + 0] = fmaf(p, vv.x, o[4 * i + 0]);
                o[4 * i + 1] = fmaf(p, vv.y, o[4 * i + 1]);
                o[4 * i + 2] = fmaf(p, vv.z, o[4 * i + 2]);
                o[4 * i + 3] = fmaf(p, vv.w, o[4 * i + 3]);
            }
        }
        m = mnew;
        __syncthreads();
    }

    float inv = 1.f / l;
    float* optr = g_o + (size_t)(b * SS + qrow) * DIM + h * HD;
#pragma unroll
    for (int d = 0; d < 64; d++) optr[d] = o[d] * inv;
}

// ---------------------------------------------------------------------------
extern "C" void kernel_launch(void* const* d_in, const int* in_sizes, int n_in,
                              void* d_out, int out_size)
{
    const float* x    = (const float*)d_in[0];
    const float* fc   = (const float*)d_in[1];
    const float* fs   = (const float*)d_in[2];
    const float* wqkv = (const float*)d_in[3];
    const float* wo   = (const float*)d_in[4];
    float* out = (float*)d_out;

    float *qkv, *o;
    cudaGetSymbolAddress((void**)&qkv, g_qkv);
    cudaGetSymbolAddress((void**)&o,   g_o);

    // 1) QKV projection: (B*S, DIM) x (ASH, DIM)^T -> (B*S, ASH)
    sgemm_nt<<<dim3(ASH / 64, (BB * SS) / 64), 256>>>(x, wqkv, qkv, BB * SS, ASH, DIM);

    // 2) RoPE on q + k
    int total = BB * SS * (NH + NKV) * HHALF;
    rope_kernel<<<(total + 255) / 256, 256>>>(fc, fs);

    // 3) causal flash attention
    flash_kernel<<<dim3(SS / 64, NH, BB), 64>>>();

    // 4) output projection: (B*S, DIM) x (DIM, DIM)^T -> (B*S, DIM)
    sgemm_nt<<<dim3(DIM / 64, (BB * SS) / 64), 256>>>(o, wo, out, BB * SS, DIM, DIM);
}

// round 2
// speedup vs baseline: 2.3674x; 2.3674x over previous
#include <cuda_runtime.h>
#include <cstdint>

#define BB 4
#define SS 1024
#define DIM 2048
#define NH 32
#define NKV 8
#define HD 64
#define QPK 4          // Q heads per KV head
#define ASH 3072       // (NH + 2*NKV) * HD
#define HHALF 32       // HD/2

// Scratch (device globals — allocation-free per harness rules)
__device__ float g_qkv[BB * SS * ASH];   // fused qkv projection output
__device__ float g_o[BB * SS * DIM];     // attention output (b,s,h*HD+d)

// ---------------------------------------------------------------------------
// TF32 tensor-core GEMM: C[M,N] = A[M,K] * B[N,K]^T
// (A row-major MxK, Bm row-major NxK -> both K-contiguous = mma row.col)
// 128x128 CTA tile, BK=16 double-buffered cp.async, 8 warps @ 64x32,
// mma.sync.aligned.m16n8k8.row.col.f32.tf32.tf32.f32, fp32 accumulate.
// Requires M,N % 128 == 0, K % 16 == 0.
// ---------------------------------------------------------------------------
#define BM 128
#define BN 128
#define BKT 16
#define SPAD 20   // BKT + 4 pad: (row*20 + k) % 32 covers all banks for frag loads

__device__ __forceinline__ uint32_t f2tf(float f) {
    uint32_t r;
    asm("cvt.rna.tf32.f32 %0, %1;" : "=r"(r) : "f"(f));
    return r;
}

__device__ __forceinline__ void cp16(void* smem, const void* gmem) {
    uint32_t sa = (uint32_t)__cvta_generic_to_shared(smem);
    asm volatile("cp.async.cg.shared.global [%0], [%1], 16;\n" :: "r"(sa), "l"(gmem));
}

__global__ __launch_bounds__(256) void tf32_gemm(
    const float* __restrict__ A, const float* __restrict__ Bm,
    float* __restrict__ C, int M, int N, int K)
{
    __shared__ float As[2][BM][SPAD];
    __shared__ float Bs[2][BN][SPAD];

    const int tid  = threadIdx.x;
    const int lane = tid & 31;
    const int warp = tid >> 5;
    const int wm = (warp >> 2) * 64;   // warp row offset (2 warps in m)
    const int wn = (warp & 3) * 32;    // warp col offset (4 warps in n)
    const int m0 = blockIdx.y * BM;
    const int n0 = blockIdx.x * BN;

    float acc[4][4][4];
#pragma unroll
    for (int mt = 0; mt < 4; mt++)
#pragma unroll
        for (int nt = 0; nt < 4; nt++)
#pragma unroll
            for (int r = 0; r < 4; r++) acc[mt][nt][r] = 0.f;

    // load mapping: 512 float4 per tile (128 rows x 4), 2 per thread
    const int lrow = tid >> 2;          // 0..63
    const int lcol = (tid & 3) * 4;     // 0,4,8,12

    const int ntiles = K / BKT;

    // prologue: stage 0
    {
        const int k0 = 0;
        cp16(&As[0][lrow     ][lcol], A  + (size_t)(m0 + lrow     ) * K + k0 + lcol);
        cp16(&As[0][lrow + 64][lcol], A  + (size_t)(m0 + lrow + 64) * K + k0 + lcol);
        cp16(&Bs[0][lrow     ][lcol], Bm + (size_t)(n0 + lrow     ) * K + k0 + lcol);
        cp16(&Bs[0][lrow + 64][lcol], Bm + (size_t)(n0 + lrow + 64) * K + k0 + lcol);
        asm volatile("cp.async.commit_group;\n");
    }
    asm volatile("cp.async.wait_group 0;\n");
    __syncthreads();

    for (int kt = 0; kt < ntiles; ++kt) {
        const int s = kt & 1;
        if (kt + 1 < ntiles) {
            const int k0 = (kt + 1) * BKT;
            const int d  = s ^ 1;
            cp16(&As[d][lrow     ][lcol], A  + (size_t)(m0 + lrow     ) * K + k0 + lcol);
            cp16(&As[d][lrow + 64][lcol], A  + (size_t)(m0 + lrow + 64) * K + k0 + lcol);
            cp16(&Bs[d][lrow     ][lcol], Bm + (size_t)(n0 + lrow     ) * K + k0 + lcol);
            cp16(&Bs[d][lrow + 64][lcol], Bm + (size_t)(n0 + lrow + 64) * K + k0 + lcol);
            asm volatile("cp.async.commit_group;\n");
        }

#pragma unroll
        for (int ks = 0; ks < BKT; ks += 8) {
            uint32_t af[4][4], bf[4][2];
            const int ar = lane >> 2;          // 0..7
            const int ac = ks + (lane & 3);    // k coord
#pragma unroll
            for (int mt = 0; mt < 4; mt++) {
                af[mt][0] = f2tf(As[s][wm + mt * 16 + ar    ][ac    ]);
                af[mt][1] = f2tf(As[s][wm + mt * 16 + ar + 8][ac    ]);
                af[mt][2] = f2tf(As[s][wm + mt * 16 + ar    ][ac + 4]);
                af[mt][3] = f2tf(As[s][wm + mt * 16 + ar + 8][ac + 4]);
            }
#pragma unroll
            for (int nt = 0; nt < 4; nt++) {
                bf[nt][0] = f2tf(Bs[s][wn + nt * 8 + ar][ac    ]);
                bf[nt][1] = f2tf(Bs[s][wn + nt * 8 + ar][ac + 4]);
            }
#pragma unroll
            for (int mt = 0; mt < 4; mt++)
#pragma unroll
                for (int nt = 0; nt < 4; nt++) {
                    asm volatile(
                        "mma.sync.aligned.m16n8k8.row.col.f32.tf32.tf32.f32 "
                        "{%0,%1,%2,%3}, {%4,%5,%6,%7}, {%8,%9}, {%0,%1,%2,%3};\n"
                        : "+f"(acc[mt][nt][0]), "+f"(acc[mt][nt][1]),
                          "+f"(acc[mt][nt][2]), "+f"(acc[mt][nt][3])
                        : "r"(af[mt][0]), "r"(af[mt][1]), "r"(af[mt][2]), "r"(af[mt][3]),
                          "r"(bf[nt][0]), "r"(bf[nt][1]));
                }
        }

        if (kt + 1 < ntiles) {
            asm volatile("cp.async.wait_group 0;\n");
            __syncthreads();
        }
    }

    // epilogue
#pragma unroll
    for (int mt = 0; mt < 4; mt++) {
#pragma unroll
        for (int nt = 0; nt < 4; nt++) {
            int row = m0 + wm + mt * 16 + (lane >> 2);
            int col = n0 + wn + nt * 8 + 2 * (lane & 3);
            float2 v01 = make_float2(acc[mt][nt][0], acc[mt][nt][1]);
            float2 v23 = make_float2(acc[mt][nt][2], acc[mt][nt][3]);
            *(float2*)&C[(size_t)row * N + col]       = v01;
            *(float2*)&C[(size_t)(row + 8) * N + col] = v23;
        }
    }
}

// ---------------------------------------------------------------------------
// RoPE on Q (32 heads) and K (8 heads), interleaved (real, imag) pairs.
// ---------------------------------------------------------------------------
__global__ void rope_kernel(const float* __restrict__ cosf,
                            const float* __restrict__ sinf)
{
    const int total = BB * SS * (NH + NKV) * HHALF;
    int idx = blockIdx.x * blockDim.x + threadIdx.x;
    if (idx >= total) return;

    int pair = idx % HHALF;
    int tmp  = idx / HHALF;
    int h    = tmp % (NH + NKV);
    tmp     /= (NH + NKV);
    int s    = tmp % SS;
    int b    = tmp / SS;

    int a;
    if (h < NH) a = (h / QPK) * ((QPK + 2) * HD) + (h % QPK) * HD;   // q head
    else        a = (h - NH) * ((QPK + 2) * HD) + QPK * HD;          // k head

    float* p = g_qkv + (size_t)(b * SS + s) * ASH + a + 2 * pair;
    float c  = cosf[s * HHALF + pair];
    float sn = sinf[s * HHALF + pair];
    float xr = p[0], xi = p[1];
    p[0] = xr * c - xi * sn;
    p[1] = xr * sn + xi * c;
}

// ---------------------------------------------------------------------------
// Causal flash attention, fp32. BM=BN=64, HD=64. (unchanged this round)
// ---------------------------------------------------------------------------
__global__ __launch_bounds__(64) void flash_kernel()
{
    __shared__ float Ks[64][64];
    __shared__ float Vs[64][64];
    __shared__ float Ss[64][64];   // [j][r]

    const int r  = threadIdx.x;
    const int qb = blockIdx.x;
    const int h  = blockIdx.y;
    const int b  = blockIdx.z;

    const int kv   = h / QPK;
    const int qoff = kv * 384 + (h % QPK) * 64;
    const int koff = kv * 384 + 256;
    const int voff = kv * 384 + 320;
    const int qrow = qb * 64 + r;

    const float* qptr = g_qkv + (size_t)(b * SS + qrow) * ASH + qoff;
    float4 q[16];
#pragma unroll
    for (int i = 0; i < 16; i++) q[i] = ((const float4*)qptr)[i];

    float o[64];
#pragma unroll
    for (int d = 0; d < 64; d++) o[d] = 0.f;
    float m = -1e30f, l = 0.f;
    const float scale = 0.125f;    // 1/sqrt(64)

    for (int kb = 0; kb <= qb; ++kb) {
        const float* kbase = g_qkv + (size_t)(b * SS + kb * 64) * ASH;
#pragma unroll
        for (int it = 0; it < 16; ++it) {
            int f   = r + it * 64;
            int row = f >> 4;
            int c4  = f & 15;
            ((float4*)Ks)[row * 16 + c4] =
                *(const float4*)(kbase + (size_t)row * ASH + koff + c4 * 4);
            ((float4*)Vs)[row * 16 + c4] =
                *(const float4*)(kbase + (size_t)row * ASH + voff + c4 * 4);
        }
        __syncthreads();

        float tmax = -1e30f;
        for (int j = 0; j < 64; ++j) {
            const float4* kj = (const float4*)Ks[j];
            float s_ = 0.f;
#pragma unroll
            for (int i = 0; i < 16; i++) {
                float4 kk = kj[i];
                s_ = fmaf(q[i].x, kk.x, s_);
                s_ = fmaf(q[i].y, kk.y, s_);
                s_ = fmaf(q[i].z, kk.z, s_);
                s_ = fmaf(q[i].w, kk.w, s_);
            }
            int kcol = kb * 64 + j;
            s_ = (kcol <= qrow) ? s_ * scale : -1e30f;
            Ss[j][r] = s_;
            tmax = fmaxf(tmax, s_);
        }

        float mnew  = fmaxf(m, tmax);
        float alpha = __expf(m - mnew);
        l *= alpha;
#pragma unroll
        for (int d = 0; d < 64; d++) o[d] *= alpha;

        for (int j = 0; j < 64; ++j) {
            float p = __expf(Ss[j][r] - mnew);
            l += p;
            const float4* vj = (const float4*)Vs[j];
#pragma unroll
            for (int i = 0; i < 16; i++) {
                float4 vv = vj[i];
                o[4 * i + 0] = fmaf(p, vv.x, o[4 * i + 0]);
                o[4 * i + 1] = fmaf(p, vv.y, o[4 * i + 1]);
                o[4 * i + 2] = fmaf(p, vv.z, o[4 * i + 2]);
                o[4 * i + 3] = fmaf(p, vv.w, o[4 * i + 3]);
            }
        }
        m = mnew;
        __syncthreads();
    }

    float inv = 1.f / l;
    float* optr = g_o + (size_t)(b * SS + qrow) * DIM + h * HD;
#pragma unroll
    for (int d = 0; d < 64; d++) optr[d] = o[d] * inv;
}

// ---------------------------------------------------------------------------
extern "C" void kernel_launch(void* const* d_in, const int* in_sizes, int n_in,
                              void* d_out, int out_size)
{
    const float* x    = (const float*)d_in[0];
    const float* fc   = (const float*)d_in[1];
    const float* fs   = (const float*)d_in[2];
    const float* wqkv = (const float*)d_in[3];
    const float* wo   = (const float*)d_in[4];
    float* out = (float*)d_out;

    float *qkv, *o;
    cudaGetSymbolAddress((void**)&qkv, g_qkv);
    cudaGetSymbolAddress((void**)&o,   g_o);

    // 1) QKV projection: (B*S, DIM) x (ASH, DIM)^T -> (B*S, ASH)  [tf32 TC]
    tf32_gemm<<<dim3(ASH / BN, (BB * SS) / BM), 256>>>(x, wqkv, qkv, BB * SS, ASH, DIM);

    // 2) RoPE on q + k
    int total = BB * SS * (NH + NKV) * HHALF;
    rope_kernel<<<(total + 255) / 256, 256>>>(fc, fs);

    // 3) causal flash attention (fp32)
    flash_kernel<<<dim3(SS / 64, NH, BB), 64>>>();

    // 4) output projection: (B*S, DIM) x (DIM, DIM)^T -> (B*S, DIM)  [tf32 TC]
    tf32_gemm<<<dim3(DIM / BN, (BB * SS) / BM), 256>>>(o, wo, out, BB * SS, DIM, DIM);
}

// round 4
// speedup vs baseline: 3.1458x; 1.3288x over previous
#include <cuda_runtime.h>
#include <cstdint>

#define BB 4
#define SS 1024
#define DIM 2048
#define NH 32
#define NKV 8
#define HD 64
#define QPK 4          // Q heads per KV head
#define ASH 3072       // (NH + 2*NKV) * HD
#define HHALF 32       // HD/2

// Scratch (device globals — allocation-free per harness rules)
__device__ float g_qkv[BB * SS * ASH];   // fused qkv projection output
__device__ float g_o[BB * SS * DIM];     // attention output (b,s,h*HD+d)

__device__ __forceinline__ uint32_t f2tf(float f) {
    uint32_t r;
    asm("cvt.rna.tf32.f32 %0, %1;" : "=r"(r) : "f"(f));
    return r;
}

// split f into tf32 hi + tf32 residual
__device__ __forceinline__ void tfsplit(float f, uint32_t& hi, uint32_t& lo) {
    hi = f2tf(f);
    lo = f2tf(f - __uint_as_float(hi));
}

__device__ __forceinline__ void mma8(float* c, const uint32_t* a, const uint32_t* b) {
    asm volatile(
        "mma.sync.aligned.m16n8k8.row.col.f32.tf32.tf32.f32 "
        "{%0,%1,%2,%3}, {%4,%5,%6,%7}, {%8,%9}, {%0,%1,%2,%3};\n"
        : "+f"(c[0]), "+f"(c[1]), "+f"(c[2]), "+f"(c[3])
        : "r"(a[0]), "r"(a[1]), "r"(a[2]), "r"(a[3]), "r"(b[0]), "r"(b[1]));
}

// ---------------------------------------------------------------------------
// TF32 tensor-core GEMM: C[M,N] = A[M,K] * B[N,K]^T  (unchanged from R2)
// ---------------------------------------------------------------------------
#define BM 128
#define BN 128
#define BKT 16
#define SPAD 20

__device__ __forceinline__ void cp16(void* smem, const void* gmem) {
    uint32_t sa = (uint32_t)__cvta_generic_to_shared(smem);
    asm volatile("cp.async.cg.shared.global [%0], [%1], 16;\n" :: "r"(sa), "l"(gmem));
}

__global__ __launch_bounds__(256) void tf32_gemm(
    const float* __restrict__ A, const float* __restrict__ Bm,
    float* __restrict__ C, int M, int N, int K)
{
    __shared__ float As[2][BM][SPAD];
    __shared__ float Bs[2][BN][SPAD];

    const int tid  = threadIdx.x;
    const int lane = tid & 31;
    const int warp = tid >> 5;
    const int wm = (warp >> 2) * 64;
    const int wn = (warp & 3) * 32;
    const int m0 = blockIdx.y * BM;
    const int n0 = blockIdx.x * BN;

    float acc[4][4][4];
#pragma unroll
    for (int mt = 0; mt < 4; mt++)
#pragma unroll
        for (int nt = 0; nt < 4; nt++)
#pragma unroll
            for (int r = 0; r < 4; r++) acc[mt][nt][r] = 0.f;

    const int lrow = tid >> 2;
    const int lcol = (tid & 3) * 4;
    const int ntiles = K / BKT;

    {
        cp16(&As[0][lrow     ][lcol], A  + (size_t)(m0 + lrow     ) * K + lcol);
        cp16(&As[0][lrow + 64][lcol], A  + (size_t)(m0 + lrow + 64) * K + lcol);
        cp16(&Bs[0][lrow     ][lcol], Bm + (size_t)(n0 + lrow     ) * K + lcol);
        cp16(&Bs[0][lrow + 64][lcol], Bm + (size_t)(n0 + lrow + 64) * K + lcol);
        asm volatile("cp.async.commit_group;\n");
    }
    asm volatile("cp.async.wait_group 0;\n");
    __syncthreads();

    for (int kt = 0; kt < ntiles; ++kt) {
        const int s = kt & 1;
        if (kt + 1 < ntiles) {
            const int k0 = (kt + 1) * BKT;
            const int d  = s ^ 1;
            cp16(&As[d][lrow     ][lcol], A  + (size_t)(m0 + lrow     ) * K + k0 + lcol);
            cp16(&As[d][lrow + 64][lcol], A  + (size_t)(m0 + lrow + 64) * K + k0 + lcol);
            cp16(&Bs[d][lrow     ][lcol], Bm + (size_t)(n0 + lrow     ) * K + k0 + lcol);
            cp16(&Bs[d][lrow + 64][lcol], Bm + (size_t)(n0 + lrow + 64) * K + k0 + lcol);
            asm volatile("cp.async.commit_group;\n");
        }

#pragma unroll
        for (int ks = 0; ks < BKT; ks += 8) {
            uint32_t af[4][4], bf[4][2];
            const int ar = lane >> 2;
            const int ac = ks + (lane & 3);
#pragma unroll
            for (int mt = 0; mt < 4; mt++) {
                af[mt][0] = f2tf(As[s][wm + mt * 16 + ar    ][ac    ]);
                af[mt][1] = f2tf(As[s][wm + mt * 16 + ar + 8][ac    ]);
                af[mt][2] = f2tf(As[s][wm + mt * 16 + ar    ][ac + 4]);
                af[mt][3] = f2tf(As[s][wm + mt * 16 + ar + 8][ac + 4]);
            }
#pragma unroll
            for (int nt = 0; nt < 4; nt++) {
                bf[nt][0] = f2tf(Bs[s][wn + nt * 8 + ar][ac    ]);
                bf[nt][1] = f2tf(Bs[s][wn + nt * 8 + ar][ac + 4]);
            }
#pragma unroll
            for (int mt = 0; mt < 4; mt++)
#pragma unroll
                for (int nt = 0; nt < 4; nt++)
                    mma8(acc[mt][nt], af[mt], bf[nt]);
        }

        if (kt + 1 < ntiles) {
            asm volatile("cp.async.wait_group 0;\n");
            __syncthreads();
        }
    }

#pragma unroll
    for (int mt = 0; mt < 4; mt++) {
#pragma unroll
        for (int nt = 0; nt < 4; nt++) {
            int row = m0 + wm + mt * 16 + (lane >> 2);
            int col = n0 + wn + nt * 8 + 2 * (lane & 3);
            *(float2*)&C[(size_t)row * N + col] =
                make_float2(acc[mt][nt][0], acc[mt][nt][1]);
            *(float2*)&C[(size_t)(row + 8) * N + col] =
                make_float2(acc[mt][nt][2], acc[mt][nt][3]);
        }
    }
}

// ---------------------------------------------------------------------------
// RoPE on Q (32 heads) and K (8 heads), interleaved (real, imag) pairs.
// ---------------------------------------------------------------------------
__global__ void rope_kernel(const float* __restrict__ cosf,
                            const float* __restrict__ sinf)
{
    const int total = BB * SS * (NH + NKV) * HHALF;
    int idx = blockIdx.x * blockDim.x + threadIdx.x;
    if (idx >= total) return;

    int pair = idx % HHALF;
    int tmp  = idx / HHALF;
    int h    = tmp % (NH + NKV);
    tmp     /= (NH + NKV);
    int s    = tmp % SS;
    int b    = tmp / SS;

    int a;
    if (h < NH) a = (h / QPK) * ((QPK + 2) * HD) + (h % QPK) * HD;
    else        a = (h - NH) * ((QPK + 2) * HD) + QPK * HD;

    float* p = g_qkv + (size_t)(b * SS + s) * ASH + a + 2 * pair;
    float c  = cosf[s * HHALF + pair];
    float sn = sinf[s * HHALF + pair];
    float xr = p[0], xi = p[1];
    p[0] = xr * c - xi * sn;
    p[1] = xr * sn + xi * c;
}

// ---------------------------------------------------------------------------
// Tensor-core causal flash attention, tf32 with 3xTF32 operand splitting
// (error ~ eps_tf32^2 => effectively fp32-accurate).
// 1 CTA per (b, h, 64-row q tile). 4 warps x 16 q rows. K/V tiles 64x64.
// Scores via mma m16n8k8 (A=Q rows, B=K rows, both d-contiguous);
// online softmax on accumulator fragments; P restaged via smem -> A frags;
// PV via mma (B = V with n=d, k=key).
// ---------------------------------------------------------------------------
#define FPAD 68

__global__ __launch_bounds__(128) void flash_tc()
{
    extern __shared__ float sm[];
    float* Qs = sm;                   // [64][FPAD]
    float* Ks = Qs + 64 * FPAD;       // [64][FPAD]  (rows = key, cols = d)
    float* Vs = Ks + 64 * FPAD;       // [64][FPAD]  (rows = key, cols = d)
    float* Ps = Vs + 64 * FPAD;       // [64][FPAD]  (rows = q, cols = key)

    const int tid  = threadIdx.x;
    const int lane = tid & 31;
    const int warp = tid >> 5;
    const int qb = blockIdx.x;
    const int h  = blockIdx.y;
    const int b  = blockIdx.z;

    const int kv   = h >> 2;
    const int qoff = kv * 384 + (h & 3) * 64;
    const int koff = kv * 384 + 256;
    const int voff = kv * 384 + 320;

    // load Q tile (64 rows x 64 d)
    const float* qbase = g_qkv + (size_t)(b * SS + qb * 64) * ASH + qoff;
#pragma unroll
    for (int it = 0; it < 8; ++it) {
        int f = tid + it * 128;
        int row = f >> 4, c4 = f & 15;
        *(float4*)&Qs[row * FPAD + c4 * 4] =
            *(const float4*)(qbase + (size_t)row * ASH + c4 * 4);
    }

    const int r0  = lane >> 2;        // 0..7
    const int q4  = lane & 3;         // 0..3
    const int w16 = warp * 16;
    const int qrow0 = qb * 64 + w16 + r0;      // rows for c0/c1
    const int qrow1 = qrow0 + 8;               // rows for c2/c3
    const float scale = 0.125f;                // 1/sqrt(64)

    float accO[8][4];
#pragma unroll
    for (int nt = 0; nt < 8; nt++)
#pragma unroll
        for (int r = 0; r < 4; r++) accO[nt][r] = 0.f;

    float mr0 = -1e30f, mr1 = -1e30f;
    float l0 = 0.f, l1 = 0.f;

    for (int kb = 0; kb <= qb; ++kb) {
        __syncthreads();   // previous tile's Ks/Vs reads complete (and Q load on kb=0)
        const float* kvb = g_qkv + (size_t)(b * SS + kb * 64) * ASH;
#pragma unroll
        for (int it = 0; it < 8; ++it) {
            int f = tid + it * 128;
            int row = f >> 4, c4 = f & 15;
            *(float4*)&Ks[row * FPAD + c4 * 4] =
                *(const float4*)(kvb + (size_t)row * ASH + koff + c4 * 4);
            *(float4*)&Vs[row * FPAD + c4 * 4] =
                *(const float4*)(kvb + (size_t)row * ASH + voff + c4 * 4);
        }
        __syncthreads();

        // ---- scores: S = Q @ K^T (3xTF32) ----
        float accS[8][4];
#pragma unroll
        for (int nt = 0; nt < 8; nt++)
#pragma unroll
            for (int r = 0; r < 4; r++) accS[nt][r] = 0.f;

#pragma unroll
        for (int kc = 0; kc < 8; ++kc) {
            const int d0 = kc * 8 + q4;
            uint32_t ah[4], ae[4];
            tfsplit(Qs[(w16 + r0    ) * FPAD + d0    ], ah[0], ae[0]);
            tfsplit(Qs[(w16 + r0 + 8) * FPAD + d0    ], ah[1], ae[1]);
            tfsplit(Qs[(w16 + r0    ) * FPAD + d0 + 4], ah[2], ae[2]);
            tfsplit(Qs[(w16 + r0 + 8) * FPAD + d0 + 4], ah[3], ae[3]);
#pragma unroll
            for (int nt = 0; nt < 8; ++nt) {
                uint32_t bh[2], be[2];
                tfsplit(Ks[(nt * 8 + r0) * FPAD + d0    ], bh[0], be[0]);
                tfsplit(Ks[(nt * 8 + r0) * FPAD + d0 + 4], bh[1], be[1]);
                mma8(accS[nt], ah, bh);
                mma8(accS[nt], ah, be);
                mma8(accS[nt], ae, bh);
            }
        }

        // ---- mask + scale + online softmax ----
        float tmax0 = -1e30f, tmax1 = -1e30f;
#pragma unroll
        for (int nt = 0; nt < 8; ++nt) {
            int kc0 = kb * 64 + nt * 8 + q4 * 2;
#pragma unroll
            for (int c = 0; c < 2; ++c) {
                float s0 = accS[nt][c]     * scale;
                float s1 = accS[nt][c + 2] * scale;
                if (kc0 + c > qrow0) s0 = -1e30f;
                if (kc0 + c > qrow1) s1 = -1e30f;
                accS[nt][c]     = s0;
                accS[nt][c + 2] = s1;
                tmax0 = fmaxf(tmax0, s0);
                tmax1 = fmaxf(tmax1, s1);
            }
        }
        tmax0 = fmaxf(tmax0, __shfl_xor_sync(0xffffffff, tmax0, 1));
        tmax0 = fmaxf(tmax0, __shfl_xor_sync(0xffffffff, tmax0, 2));
        tmax1 = fmaxf(tmax1, __shfl_xor_sync(0xffffffff, tmax1, 1));
        tmax1 = fmaxf(tmax1, __shfl_xor_sync(0xffffffff, tmax1, 2));

        float mn0 = fmaxf(mr0, tmax0);
        float mn1 = fmaxf(mr1, tmax1);
        float al0 = __expf(mr0 - mn0);
        float al1 = __expf(mr1 - mn1);
        mr0 = mn0; mr1 = mn1;

        float ls0 = 0.f, ls1 = 0.f;
#pragma unroll
        for (int nt = 0; nt < 8; ++nt) {
            float p0 = __expf(accS[nt][0] - mn0);
            float p1 = __expf(accS[nt][1] - mn0);
            float p2 = __expf(accS[nt][2] - mn1);
            float p3 = __expf(accS[nt][3] - mn1);
            ls0 += p0 + p1;
            ls1 += p2 + p3;
            int col = nt * 8 + q4 * 2;
            *(float2*)&Ps[(w16 + r0    ) * FPAD + col] = make_float2(p0, p1);
            *(float2*)&Ps[(w16 + r0 + 8) * FPAD + col] = make_float2(p2, p3);
        }
        l0 = l0 * al0 + ls0;
        l1 = l1 * al1 + ls1;

#pragma unroll
        for (int nt = 0; nt < 8; ++nt) {
            accO[nt][0] *= al0; accO[nt][1] *= al0;
            accO[nt][2] *= al1; accO[nt][3] *= al1;
        }
        __syncwarp();

        // ---- PV: O += P @ V (3xTF32); B frag: n = d, k = key ----
#pragma unroll
        for (int kc = 0; kc < 8; ++kc) {
            const int k0 = kc * 8 + q4;
            uint32_t ph[4], pe[4];
            tfsplit(Ps[(w16 + r0    ) * FPAD + k0    ], ph[0], pe[0]);
            tfsplit(Ps[(w16 + r0 + 8) * FPAD + k0    ], ph[1], pe[1]);
            tfsplit(Ps[(w16 + r0    ) * FPAD + k0 + 4], ph[2], pe[2]);
            tfsplit(Ps[(w16 + r0 + 8) * FPAD + k0 + 4], ph[3], pe[3]);
#pragma unroll
            for (int nt = 0; nt < 8; ++nt) {
                uint32_t vh[2], ve[2];
                tfsplit(Vs[(k0    ) * FPAD + nt * 8 + r0], vh[0], ve[0]);
                tfsplit(Vs[(k0 + 4) * FPAD + nt * 8 + r0], vh[1], ve[1]);
                mma8(accO[nt], ph, vh);
                mma8(accO[nt], ph, ve);
                mma8(accO[nt], pe, vh);
            }
        }
    }

    // ---- finalize ----
    l0 += __shfl_xor_sync(0xffffffff, l0, 1);
    l0 += __shfl_xor_sync(0xffffffff, l0, 2);
    l1 += __shfl_xor_sync(0xffffffff, l1, 1);
    l1 += __shfl_xor_sync(0xffffffff, l1, 2);
    float inv0 = 1.f / l0;
    float inv1 = 1.f / l1;

    float* ob0 = g_o + (size_t)(b * SS + qrow0) * DIM + h * HD;
    float* ob1 = g_o + (size_t)(b * SS + qrow1) * DIM + h * HD;
#pragma unroll
    for (int nt = 0; nt < 8; ++nt) {
        int col = nt * 8 + q4 * 2;
        *(float2*)&ob0[col] = make_float2(accO[nt][0] * inv0, accO[nt][1] * inv0);
        *(float2*)&ob1[col] = make_float2(accO[nt][2] * inv1, accO[nt][3] * inv1);
    }
}

// ---------------------------------------------------------------------------
extern "C" void kernel_launch(void* const* d_in, const int* in_sizes, int n_in,
                              void* d_out, int out_size)
{
    const float* x    = (const float*)d_in[0];
    const float* fc   = (const float*)d_in[1];
    const float* fs   = (const float*)d_in[2];
    const float* wqkv = (const float*)d_in[3];
    const float* wo   = (const float*)d_in[4];
    float* out = (float*)d_out;

    float *qkv, *o;
    cudaGetSymbolAddress((void**)&qkv, g_qkv);
    cudaGetSymbolAddress((void**)&o,   g_o);

    const int flash_smem = 4 * 64 * FPAD * sizeof(float);  // 69,632 B
    cudaFuncSetAttribute(flash_tc, cudaFuncAttributeMaxDynamicSharedMemorySize,
                         flash_smem);

    // 1) QKV projection  [tf32 TC]
    tf32_gemm<<<dim3(ASH / BN, (BB * SS) / BM), 256>>>(x, wqkv, qkv, BB * SS, ASH, DIM);

    // 2) RoPE on q + k
    int total = BB * SS * (NH + NKV) * HHALF;
    rope_kernel<<<(total + 255) / 256, 256>>>(fc, fs);

    // 3) causal flash attention  [tf32 TC, 3xTF32 accuracy]
    flash_tc<<<dim3(SS / 64, NH, BB), 128, flash_smem>>>();

    // 4) output projection  [tf32 TC]
    tf32_gemm<<<dim3(DIM / BN, (BB * SS) / BM), 256>>>(o, wo, out, BB * SS, DIM, DIM);
}

// round 6
// speedup vs baseline: 3.5819x; 1.1386x over previous
#include <cuda_runtime.h>
#include <cuda_bf16.h>
#include <cstdint>

#define BB 4
#define SS 1024
#define DIM 2048
#define NH 32
#define NKV 8
#define HD 64
#define QPK 4
#define ASH 3072
#define HHALF 32

// Scratch (device globals — allocation-free per harness rules)
__device__ float g_qkv[BB * SS * ASH];
__device__ float g_o[BB * SS * DIM];       // attention out, tf32-rounded at write
__device__ float g_xr[BB * SS * DIM];      // tf32-rounded x
__device__ float g_wqkvr[ASH * DIM];       // tf32-rounded wqkv
__device__ float g_wor[DIM * DIM];         // tf32-rounded wo

__device__ __forceinline__ uint32_t f2tf(float f) {
    uint32_t r;
    asm("cvt.rna.tf32.f32 %0, %1;" : "=r"(r) : "f"(f));
    return r;
}

__device__ __forceinline__ void mma8(float* c, const uint32_t* a, const uint32_t* b) {
    asm volatile(
        "mma.sync.aligned.m16n8k8.row.col.f32.tf32.tf32.f32 "
        "{%0,%1,%2,%3}, {%4,%5,%6,%7}, {%8,%9}, {%0,%1,%2,%3};\n"
        : "+f"(c[0]), "+f"(c[1]), "+f"(c[2]), "+f"(c[3])
        : "r"(a[0]), "r"(a[1]), "r"(a[2]), "r"(a[3]), "r"(b[0]), "r"(b[1]));
}

__device__ __forceinline__ void mma16(float* c, const uint32_t* a, const uint32_t* b) {
    asm volatile(
        "mma.sync.aligned.m16n8k16.row.col.f32.bf16.bf16.f32 "
        "{%0,%1,%2,%3}, {%4,%5,%6,%7}, {%8,%9}, {%0,%1,%2,%3};\n"
        : "+f"(c[0]), "+f"(c[1]), "+f"(c[2]), "+f"(c[3])
        : "r"(a[0]), "r"(a[1]), "r"(a[2]), "r"(a[3]), "r"(b[0]), "r"(b[1]));
}

// ---------------------------------------------------------------------------
// Prepass: round-copy fp32 -> tf32-rounded fp32 (vectorized)
// ---------------------------------------------------------------------------
__global__ void round_tf32(const float* __restrict__ in, float* __restrict__ out, int n4)
{
    int i = blockIdx.x * blockDim.x + threadIdx.x;
    if (i >= n4) return;
    float4 v = ((const float4*)in)[i];
    v.x = __uint_as_float(f2tf(v.x));
    v.y = __uint_as_float(f2tf(v.y));
    v.z = __uint_as_float(f2tf(v.z));
    v.w = __uint_as_float(f2tf(v.w));
    ((float4*)out)[i] = v;
}

// ---------------------------------------------------------------------------
// TF32 tensor-core GEMM on pre-rounded inputs: C = A * B^T. No in-loop cvt.
// ---------------------------------------------------------------------------
#define BM 128
#define BN 128
#define BKT 16
#define SPAD 20

__device__ __forceinline__ void cp16(void* smem, const void* gmem) {
    uint32_t sa = (uint32_t)__cvta_generic_to_shared(smem);
    asm volatile("cp.async.cg.shared.global [%0], [%1], 16;\n" :: "r"(sa), "l"(gmem));
}

__global__ __launch_bounds__(256) void tf32_gemm_raw(
    const float* __restrict__ A, const float* __restrict__ Bm,
    float* __restrict__ C, int M, int N, int K)
{
    __shared__ float As[2][BM][SPAD];
    __shared__ float Bs[2][BN][SPAD];

    const int tid  = threadIdx.x;
    const int lane = tid & 31;
    const int warp = tid >> 5;
    const int wm = (warp >> 2) * 64;
    const int wn = (warp & 3) * 32;
    const int m0 = blockIdx.y * BM;
    const int n0 = blockIdx.x * BN;

    float acc[4][4][4];
#pragma unroll
    for (int mt = 0; mt < 4; mt++)
#pragma unroll
        for (int nt = 0; nt < 4; nt++)
#pragma unroll
            for (int r = 0; r < 4; r++) acc[mt][nt][r] = 0.f;

    const int lrow = tid >> 2;
    const int lcol = (tid & 3) * 4;
    const int ntiles = K / BKT;

    {
        cp16(&As[0][lrow     ][lcol], A  + (size_t)(m0 + lrow     ) * K + lcol);
        cp16(&As[0][lrow + 64][lcol], A  + (size_t)(m0 + lrow + 64) * K + lcol);
        cp16(&Bs[0][lrow     ][lcol], Bm + (size_t)(n0 + lrow     ) * K + lcol);
        cp16(&Bs[0][lrow + 64][lcol], Bm + (size_t)(n0 + lrow + 64) * K + lcol);
        asm volatile("cp.async.commit_group;\n");
    }
    asm volatile("cp.async.wait_group 0;\n");
    __syncthreads();

    for (int kt = 0; kt < ntiles; ++kt) {
        const int s = kt & 1;
        if (kt + 1 < ntiles) {
            const int k0 = (kt + 1) * BKT;
            const int d  = s ^ 1;
            cp16(&As[d][lrow     ][lcol], A  + (size_t)(m0 + lrow     ) * K + k0 + lcol);
            cp16(&As[d][lrow + 64][lcol], A  + (size_t)(m0 + lrow + 64) * K + k0 + lcol);
            cp16(&Bs[d][lrow     ][lcol], Bm + (size_t)(n0 + lrow     ) * K + k0 + lcol);
            cp16(&Bs[d][lrow + 64][lcol], Bm + (size_t)(n0 + lrow + 64) * K + k0 + lcol);
            asm volatile("cp.async.commit_group;\n");
        }

#pragma unroll
        for (int ks = 0; ks < BKT; ks += 8) {
            uint32_t af[4][4], bf[4][2];
            const int ar = lane >> 2;
            const int ac = ks + (lane & 3);
#pragma unroll
            for (int mt = 0; mt < 4; mt++) {
                af[mt][0] = __float_as_uint(As[s][wm + mt * 16 + ar    ][ac    ]);
                af[mt][1] = __float_as_uint(As[s][wm + mt * 16 + ar + 8][ac    ]);
                af[mt][2] = __float_as_uint(As[s][wm + mt * 16 + ar    ][ac + 4]);
                af[mt][3] = __float_as_uint(As[s][wm + mt * 16 + ar + 8][ac + 4]);
            }
#pragma unroll
            for (int nt = 0; nt < 4; nt++) {
                bf[nt][0] = __float_as_uint(Bs[s][wn + nt * 8 + ar][ac    ]);
                bf[nt][1] = __float_as_uint(Bs[s][wn + nt * 8 + ar][ac + 4]);
            }
#pragma unroll
            for (int mt = 0; mt < 4; mt++)
#pragma unroll
                for (int nt = 0; nt < 4; nt++)
                    mma8(acc[mt][nt], af[mt], bf[nt]);
        }

        if (kt + 1 < ntiles) {
            asm volatile("cp.async.wait_group 0;\n");
            __syncthreads();
        }
    }

#pragma unroll
    for (int mt = 0; mt < 4; mt++) {
#pragma unroll
        for (int nt = 0; nt < 4; nt++) {
            int row = m0 + wm + mt * 16 + (lane >> 2);
            int col = n0 + wn + nt * 8 + 2 * (lane & 3);
            *(float2*)&C[(size_t)row * N + col] =
                make_float2(acc[mt][nt][0], acc[mt][nt][1]);
            *(float2*)&C[(size_t)(row + 8) * N + col] =
                make_float2(acc[mt][nt][2], acc[mt][nt][3]);
        }
    }
}

// ---------------------------------------------------------------------------
// RoPE on Q + K (interleaved pairs)
// ---------------------------------------------------------------------------
__global__ void rope_kernel(const float* __restrict__ cosf,
                            const float* __restrict__ sinf)
{
    const int total = BB * SS * (NH + NKV) * HHALF;
    int idx = blockIdx.x * blockDim.x + threadIdx.x;
    if (idx >= total) return;

    int pair = idx % HHALF;
    int tmp  = idx / HHALF;
    int h    = tmp % (NH + NKV);
    tmp     /= (NH + NKV);
    int s    = tmp % SS;
    int b    = tmp / SS;

    int a;
    if (h < NH) a = (h / QPK) * ((QPK + 2) * HD) + (h % QPK) * HD;
    else        a = (h - NH) * ((QPK + 2) * HD) + QPK * HD;

    float* p = g_qkv + (size_t)(b * SS + s) * ASH + a + 2 * pair;
    float c  = cosf[s * HHALF + pair];
    float sn = sinf[s * HHALF + pair];
    float xr = p[0], xi = p[1];
    p[0] = xr * c - xi * sn;
    p[1] = xr * sn + xi * c;
}

// ---------------------------------------------------------------------------
// Flash attention with bf16 double-split (bf16x3): all operands pre-split
// into bf16 hi/lo tiles in smem; inner loops are pure lds.b32 + mma.bf16.k16.
// Error of dropped lo*lo term ~2^-18 -> effectively fp32-accurate.
// 1 CTA / (b, h, 64-row q tile); 4 warps x 16 q rows.
// ---------------------------------------------------------------------------
#define BP 72                       // bf16 row pitch (64 + 8): frag reads conflict-free
#define TS (64 * BP)                // tile elems

__device__ __forceinline__ void bsplit(float f, __nv_bfloat16& hi, __nv_bfloat16& lo) {
    hi = __float2bfloat16_rn(f);
    lo = __float2bfloat16_rn(f - __bfloat162float(hi));
}

__global__ __launch_bounds__(128) void flash_bf16()
{
    extern __shared__ __nv_bfloat16 smb[];
    __nv_bfloat16* Qh  = smb;
    __nv_bfloat16* Ql  = Qh  + TS;
    __nv_bfloat16* Kh  = Ql  + TS;
    __nv_bfloat16* Kl  = Kh  + TS;
    __nv_bfloat16* Vth = Kl  + TS;  // transposed: rows=d, cols=key
    __nv_bfloat16* Vtl = Vth + TS;
    __nv_bfloat16* Ph  = Vtl + TS;
    __nv_bfloat16* Pl  = Ph  + TS;

    const int tid  = threadIdx.x;
    const int lane = tid & 31;
    const int warp = tid >> 5;
    const int qb = blockIdx.x;
    const int h  = blockIdx.y;
    const int b  = blockIdx.z;

    const int kv   = h >> 2;
    const int qoff = kv * 384 + (h & 3) * 64;
    const int koff = kv * 384 + 256;
    const int voff = kv * 384 + 320;

    // ---- load + split Q tile ----
    const float* qbase = g_qkv + (size_t)(b * SS + qb * 64) * ASH + qoff;
#pragma unroll
    for (int it = 0; it < 8; ++it) {
        int f = tid + it * 128;
        int row = f >> 4, c4 = f & 15;
        float4 v = *(const float4*)(qbase + (size_t)row * ASH + c4 * 4);
        __nv_bfloat16 h0, l0, h1, l1, h2, l2, h3, l3;
        bsplit(v.x, h0, l0); bsplit(v.y, h1, l1);
        bsplit(v.z, h2, l2); bsplit(v.w, h3, l3);
        int o = row * BP + c4 * 4;
        Qh[o] = h0; Qh[o+1] = h1; Qh[o+2] = h2; Qh[o+3] = h3;
        Ql[o] = l0; Ql[o+1] = l1; Ql[o+2] = l2; Ql[o+3] = l3;
    }

    const int r0  = lane >> 2;
    const int q4  = lane & 3;
    const int w16 = warp * 16;
    const int qrow0 = qb * 64 + w16 + r0;
    const int qrow1 = qrow0 + 8;
    const float scale = 0.125f;

    float accO[8][4];
#pragma unroll
    for (int nt = 0; nt < 8; nt++)
#pragma unroll
        for (int r = 0; r < 4; r++) accO[nt][r] = 0.f;

    float mr0 = -1e30f, mr1 = -1e30f;
    float l0s = 0.f, l1s = 0.f;

    for (int kb = 0; kb <= qb; ++kb) {
        __syncthreads();
        const float* kvb = g_qkv + (size_t)(b * SS + kb * 64) * ASH;
#pragma unroll
        for (int it = 0; it < 8; ++it) {
            int f = tid + it * 128;
            int row = f >> 4, c4 = f & 15;
            float4 kk = *(const float4*)(kvb + (size_t)row * ASH + koff + c4 * 4);
            float4 vv = *(const float4*)(kvb + (size_t)row * ASH + voff + c4 * 4);
            __nv_bfloat16 h0, lo0, h1, lo1, h2, lo2, h3, lo3;
            bsplit(kk.x, h0, lo0); bsplit(kk.y, h1, lo1);
            bsplit(kk.z, h2, lo2); bsplit(kk.w, h3, lo3);
            int o = row * BP + c4 * 4;
            Kh[o] = h0; Kh[o+1] = h1; Kh[o+2] = h2; Kh[o+3] = h3;
            Kl[o] = lo0; Kl[o+1] = lo1; Kl[o+2] = lo2; Kl[o+3] = lo3;
            // V transposed: Vt[d][key]
            bsplit(vv.x, h0, lo0); bsplit(vv.y, h1, lo1);
            bsplit(vv.z, h2, lo2); bsplit(vv.w, h3, lo3);
            int d0 = c4 * 4;
            Vth[(d0    ) * BP + row] = h0;  Vtl[(d0    ) * BP + row] = lo0;
            Vth[(d0 + 1) * BP + row] = h1;  Vtl[(d0 + 1) * BP + row] = lo1;
            Vth[(d0 + 2) * BP + row] = h2;  Vtl[(d0 + 2) * BP + row] = lo2;
            Vth[(d0 + 3) * BP + row] = h3;  Vtl[(d0 + 3) * BP + row] = lo3;
        }
        __syncthreads();

        // ---- scores: S = Q @ K^T ----
        float accS[8][4];
#pragma unroll
        for (int nt = 0; nt < 8; nt++)
#pragma unroll
            for (int r = 0; r < 4; r++) accS[nt][r] = 0.f;

#pragma unroll
        for (int kc = 0; kc < 4; ++kc) {
            const int kq = kc * 16 + 2 * q4;
            uint32_t qh[4], ql[4];
            qh[0] = *(const uint32_t*)&Qh[(w16 + r0    ) * BP + kq    ];
            qh[1] = *(const uint32_t*)&Qh[(w16 + r0 + 8) * BP + kq    ];
            qh[2] = *(const uint32_t*)&Qh[(w16 + r0    ) * BP + kq + 8];
            qh[3] = *(const uint32_t*)&Qh[(w16 + r0 + 8) * BP + kq + 8];
            ql[0] = *(const uint32_t*)&Ql[(w16 + r0    ) * BP + kq    ];
            ql[1] = *(const uint32_t*)&Ql[(w16 + r0 + 8) * BP + kq    ];
            ql[2] = *(const uint32_t*)&Ql[(w16 + r0    ) * BP + kq + 8];
            ql[3] = *(const uint32_t*)&Ql[(w16 + r0 + 8) * BP + kq + 8];
#pragma unroll
            for (int nt = 0; nt < 8; ++nt) {
                const int rb = (nt * 8 + r0) * BP;
                uint32_t kh[2], kl[2];
                kh[0] = *(const uint32_t*)&Kh[rb + kq    ];
                kh[1] = *(const uint32_t*)&Kh[rb + kq + 8];
                kl[0] = *(const uint32_t*)&Kl[rb + kq    ];
                kl[1] = *(const uint32_t*)&Kl[rb + kq + 8];
                mma16(accS[nt], qh, kh);
                mma16(accS[nt], qh, kl);
                mma16(accS[nt], ql, kh);
            }
        }

        // ---- mask + scale + online softmax ----
        float tmax0 = -1e30f, tmax1 = -1e30f;
#pragma unroll
        for (int nt = 0; nt < 8; ++nt) {
            int kc0 = kb * 64 + nt * 8 + q4 * 2;
#pragma unroll
            for (int c = 0; c < 2; ++c) {
                float s0 = accS[nt][c]     * scale;
                float s1 = accS[nt][c + 2] * scale;
                if (kc0 + c > qrow0) s0 = -1e30f;
                if (kc0 + c > qrow1) s1 = -1e30f;
                accS[nt][c]     = s0;
                accS[nt][c + 2] = s1;
                tmax0 = fmaxf(tmax0, s0);
                tmax1 = fmaxf(tmax1, s1);
            }
        }
        tmax0 = fmaxf(tmax0, __shfl_xor_sync(0xffffffff, tmax0, 1));
        tmax0 = fmaxf(tmax0, __shfl_xor_sync(0xffffffff, tmax0, 2));
        tmax1 = fmaxf(tmax1, __shfl_xor_sync(0xffffffff, tmax1, 1));
        tmax1 = fmaxf(tmax1, __shfl_xor_sync(0xffffffff, tmax1, 2));

        float mn0 = fmaxf(mr0, tmax0);
        float mn1 = fmaxf(mr1, tmax1);
        float al0 = __expf(mr0 - mn0);
        float al1 = __expf(mr1 - mn1);
        mr0 = mn0; mr1 = mn1;

        float ls0 = 0.f, ls1 = 0.f;
#pragma unroll
        for (int nt = 0; nt < 8; ++nt) {
            float p0 = __expf(accS[nt][0] - mn0);
            float p1 = __expf(accS[nt][1] - mn0);
            float p2 = __expf(accS[nt][2] - mn1);
            float p3 = __expf(accS[nt][3] - mn1);
            ls0 += p0 + p1;
            ls1 += p2 + p3;
            int col = nt * 8 + q4 * 2;
            __nv_bfloat16 h0, lo0, h1, lo1;
            bsplit(p0, h0, lo0); bsplit(p1, h1, lo1);
            *(__nv_bfloat162*)&Ph[(w16 + r0) * BP + col] = __nv_bfloat162(h0, h1);
            *(__nv_bfloat162*)&Pl[(w16 + r0) * BP + col] = __nv_bfloat162(lo0, lo1);
            bsplit(p2, h0, lo0); bsplit(p3, h1, lo1);
            *(__nv_bfloat162*)&Ph[(w16 + r0 + 8) * BP + col] = __nv_bfloat162(h0, h1);
            *(__nv_bfloat162*)&Pl[(w16 + r0 + 8) * BP + col] = __nv_bfloat162(lo0, lo1);
        }
        l0s = l0s * al0 + ls0;
        l1s = l1s * al1 + ls1;

#pragma unroll
        for (int nt = 0; nt < 8; ++nt) {
            accO[nt][0] *= al0; accO[nt][1] *= al0;
            accO[nt][2] *= al1; accO[nt][3] *= al1;
        }
        __syncwarp();

        // ---- PV: O += P @ V ----
#pragma unroll
        for (int kc = 0; kc < 4; ++kc) {
            const int kk = kc * 16 + 2 * q4;
            uint32_t ph[4], pl[4];
            ph[0] = *(const uint32_t*)&Ph[(w16 + r0    ) * BP + kk    ];
            ph[1] = *(const uint32_t*)&Ph[(w16 + r0 + 8) * BP + kk    ];
            ph[2] = *(const uint32_t*)&Ph[(w16 + r0    ) * BP + kk + 8];
            ph[3] = *(const uint32_t*)&Ph[(w16 + r0 + 8) * BP + kk + 8];
            pl[0] = *(const uint32_t*)&Pl[(w16 + r0    ) * BP + kk    ];
            pl[1] = *(const uint32_t*)&Pl[(w16 + r0 + 8) * BP + kk    ];
            pl[2] = *(const uint32_t*)&Pl[(w16 + r0    ) * BP + kk + 8];
            pl[3] = *(const uint32_t*)&Pl[(w16 + r0 + 8) * BP + kk + 8];
#pragma unroll
            for (int nt = 0; nt < 8; ++nt) {
                const int rb = (nt * 8 + r0) * BP;   // row = d
                uint32_t vh[2], vl[2];
                vh[0] = *(const uint32_t*)&Vth[rb + kk    ];
                vh[1] = *(const uint32_t*)&Vth[rb + kk + 8];
                vl[0] = *(const uint32_t*)&Vtl[rb + kk    ];
                vl[1] = *(const uint32_t*)&Vtl[rb + kk + 8];
                mma16(accO[nt], ph, vh);
                mma16(accO[nt], ph, vl);
                mma16(accO[nt], pl, vh);
            }
        }
    }

    // ---- finalize (tf32-round o so WO gemm needs no cvt) ----
    l0s += __shfl_xor_sync(0xffffffff, l0s, 1);
    l0s += __shfl_xor_sync(0xffffffff, l0s, 2);
    l1s += __shfl_xor_sync(0xffffffff, l1s, 1);
    l1s += __shfl_xor_sync(0xffffffff, l1s, 2);
    float inv0 = 1.f / l0s;
    float inv1 = 1.f / l1s;

    float* ob0 = g_o + (size_t)(b * SS + qrow0) * DIM + h * HD;
    float* ob1 = g_o + (size_t)(b * SS + qrow1) * DIM + h * HD;
#pragma unroll
    for (int nt = 0; nt < 8; ++nt) {
        int col = nt * 8 + q4 * 2;
        *(float2*)&ob0[col] = make_float2(
            __uint_as_float(f2tf(accO[nt][0] * inv0)),
            __uint_as_float(f2tf(accO[nt][1] * inv0)));
        *(float2*)&ob1[col] = make_float2(
            __uint_as_float(f2tf(accO[nt][2] * inv1)),
            __uint_as_float(f2tf(accO[nt][3] * inv1)));
    }
}

// ---------------------------------------------------------------------------
extern "C" void kernel_launch(void* const* d_in, const int* in_sizes, int n_in,
                              void* d_out, int out_size)
{
    const float* x    = (const float*)d_in[0];
    const float* fc   = (const float*)d_in[1];
    const float* fs   = (const float*)d_in[2];
    const float* wqkv = (const float*)d_in[3];
    const float* wo   = (const float*)d_in[4];
    float* out = (float*)d_out;

    float *qkv, *o, *xr, *wqkvr, *wor;
    cudaGetSymbolAddress((void**)&qkv,   g_qkv);
    cudaGetSymbolAddress((void**)&o,     g_o);
    cudaGetSymbolAddress((void**)&xr,    g_xr);
    cudaGetSymbolAddress((void**)&wqkvr, g_wqkvr);
    cudaGetSymbolAddress((void**)&wor,   g_wor);

    const int flash_smem = 8 * TS * sizeof(__nv_bfloat16);  // 73,728 B
    cudaFuncSetAttribute(flash_bf16, cudaFuncAttributeMaxDynamicSharedMemorySize,
                         flash_smem);

    // 0) tf32-round inputs (removes all cvt from GEMM hot loops)
    {
        int n4;
        n4 = BB * SS * DIM / 4;
        round_tf32<<<(n4 + 255) / 256, 256>>>(x, xr, n4);
        n4 = ASH * DIM / 4;
        round_tf32<<<(n4 + 255) / 256, 256>>>(wqkv, wqkvr, n4);
        n4 = DIM * DIM / 4;
        round_tf32<<<(n4 + 255) / 256, 256>>>(wo, wor, n4);
    }

    // 1) QKV projection  [tf32 TC, raw operands]
    tf32_gemm_raw<<<dim3(ASH / BN, (BB * SS) / BM), 256>>>(xr, wqkvr, qkv, BB * SS, ASH, DIM);

    // 2) RoPE
    int total = BB * SS * (NH + NKV) * HHALF;
    rope_kernel<<<(total + 255) / 256, 256>>>(fc, fs);

    // 3) causal flash attention  [bf16x3 TC]
    flash_bf16<<<dim3(SS / 64, NH, BB), 128, flash_smem>>>();

    // 4) output projection  [tf32 TC, raw operands]
    tf32_gemm_raw<<<dim3(DIM / BN, (BB * SS) / BM), 256>>>(o, wor, out, BB * SS, DIM, DIM);
}

// round 7
// speedup vs baseline: 3.8249x; 1.0679x over previous
#include <cuda_runtime.h>
#include <cuda_bf16.h>
#include <cstdint>

#define BB 4
#define SS 1024
#define DIM 2048
#define NH 32
#define NKV 8
#define HD 64
#define QPK 4
#define ASH 3072
#define HHALF 32

// Scratch (device globals — allocation-free per harness rules)
__device__ float g_qkv[BB * SS * ASH];
__device__ float g_o[BB * SS * DIM];       // attention out, tf32-rounded at write
__device__ float g_xr[BB * SS * DIM];      // tf32-rounded x
__device__ float g_wqkvr[ASH * DIM];       // tf32-rounded wqkv
__device__ float g_wor[DIM * DIM];         // tf32-rounded wo

__device__ __forceinline__ uint32_t f2tf(float f) {
    uint32_t r;
    asm("cvt.rna.tf32.f32 %0, %1;" : "=r"(r) : "f"(f));
    return r;
}

__device__ __forceinline__ void mma8(float* c, const uint32_t* a, const uint32_t* b) {
    asm volatile(
        "mma.sync.aligned.m16n8k8.row.col.f32.tf32.tf32.f32 "
        "{%0,%1,%2,%3}, {%4,%5,%6,%7}, {%8,%9}, {%0,%1,%2,%3};\n"
        : "+f"(c[0]), "+f"(c[1]), "+f"(c[2]), "+f"(c[3])
        : "r"(a[0]), "r"(a[1]), "r"(a[2]), "r"(a[3]), "r"(b[0]), "r"(b[1]));
}

__device__ __forceinline__ void mma16(float* c, const uint32_t* a, const uint32_t* b) {
    asm volatile(
        "mma.sync.aligned.m16n8k16.row.col.f32.bf16.bf16.f32 "
        "{%0,%1,%2,%3}, {%4,%5,%6,%7}, {%8,%9}, {%0,%1,%2,%3};\n"
        : "+f"(c[0]), "+f"(c[1]), "+f"(c[2]), "+f"(c[3])
        : "r"(a[0]), "r"(a[1]), "r"(a[2]), "r"(a[3]), "r"(b[0]), "r"(b[1]));
}

// ---------------------------------------------------------------------------
// Prepass: round-copy fp32 -> tf32-rounded fp32
// ---------------------------------------------------------------------------
__global__ void round_tf32(const float* __restrict__ in, float* __restrict__ out, int n4)
{
    int i = blockIdx.x * blockDim.x + threadIdx.x;
    if (i >= n4) return;
    float4 v = ((const float4*)in)[i];
    v.x = __uint_as_float(f2tf(v.x));
    v.y = __uint_as_float(f2tf(v.y));
    v.z = __uint_as_float(f2tf(v.z));
    v.w = __uint_as_float(f2tf(v.w));
    ((float4*)out)[i] = v;
}

// ---------------------------------------------------------------------------
// TF32 TC GEMM, 3-stage cp.async pipeline: C = A * B^T (pre-rounded inputs)
// ---------------------------------------------------------------------------
#define BM 128
#define BN 128
#define BKT 16
#define SPAD 20
#define GSTAGE 3
#define GEMM_SMEM (GSTAGE * (BM + BN) * SPAD * 4)   // 61,440 B

__device__ __forceinline__ void cp16(void* smem, const void* gmem) {
    uint32_t sa = (uint32_t)__cvta_generic_to_shared(smem);
    asm volatile("cp.async.cg.shared.global [%0], [%1], 16;\n" :: "r"(sa), "l"(gmem));
}

__global__ __launch_bounds__(256) void tf32_gemm_p3(
    const float* __restrict__ A, const float* __restrict__ Bm,
    float* __restrict__ C, int M, int N, int K)
{
    extern __shared__ float gsm[];

    const int tid  = threadIdx.x;
    const int lane = tid & 31;
    const int warp = tid >> 5;
    const int wm = (warp >> 2) * 64;
    const int wn = (warp & 3) * 32;
    const int m0 = blockIdx.y * BM;
    const int n0 = blockIdx.x * BN;

    float acc[4][4][4];
#pragma unroll
    for (int mt = 0; mt < 4; mt++)
#pragma unroll
        for (int nt = 0; nt < 4; nt++)
#pragma unroll
            for (int r = 0; r < 4; r++) acc[mt][nt][r] = 0.f;

    const int lrow = tid >> 2;
    const int lcol = (tid & 3) * 4;
    const int ntiles = K / BKT;

    auto load_stage = [&](int s, int k0) {
        float* as = gsm + s * (BM + BN) * SPAD;
        float* bs = as + BM * SPAD;
        cp16(as + (lrow     ) * SPAD + lcol, A  + (size_t)(m0 + lrow     ) * K + k0 + lcol);
        cp16(as + (lrow + 64) * SPAD + lcol, A  + (size_t)(m0 + lrow + 64) * K + k0 + lcol);
        cp16(bs + (lrow     ) * SPAD + lcol, Bm + (size_t)(n0 + lrow     ) * K + k0 + lcol);
        cp16(bs + (lrow + 64) * SPAD + lcol, Bm + (size_t)(n0 + lrow + 64) * K + k0 + lcol);
        asm volatile("cp.async.commit_group;\n");
    };

    load_stage(0, 0);
    load_stage(1, BKT);

    for (int kt = 0; kt < ntiles; ++kt) {
        if (kt + 1 < ntiles) asm volatile("cp.async.wait_group 1;\n");
        else                 asm volatile("cp.async.wait_group 0;\n");
        __syncthreads();

        if (kt + 2 < ntiles) load_stage((kt + 2) % GSTAGE, (kt + 2) * BKT);

        const float* as = gsm + (kt % GSTAGE) * (BM + BN) * SPAD;
        const float* bs = as + BM * SPAD;

#pragma unroll
        for (int ks = 0; ks < BKT; ks += 8) {
            uint32_t af[4][4], bf[4][2];
            const int ar = lane >> 2;
            const int ac = ks + (lane & 3);
#pragma unroll
            for (int mt = 0; mt < 4; mt++) {
                af[mt][0] = __float_as_uint(as[(wm + mt * 16 + ar    ) * SPAD + ac    ]);
                af[mt][1] = __float_as_uint(as[(wm + mt * 16 + ar + 8) * SPAD + ac    ]);
                af[mt][2] = __float_as_uint(as[(wm + mt * 16 + ar    ) * SPAD + ac + 4]);
                af[mt][3] = __float_as_uint(as[(wm + mt * 16 + ar + 8) * SPAD + ac + 4]);
            }
#pragma unroll
            for (int nt = 0; nt < 4; nt++) {
                bf[nt][0] = __float_as_uint(bs[(wn + nt * 8 + ar) * SPAD + ac    ]);
                bf[nt][1] = __float_as_uint(bs[(wn + nt * 8 + ar) * SPAD + ac + 4]);
            }
#pragma unroll
            for (int mt = 0; mt < 4; mt++)
#pragma unroll
                for (int nt = 0; nt < 4; nt++)
                    mma8(acc[mt][nt], af[mt], bf[nt]);
        }
        __syncthreads();
    }

#pragma unroll
    for (int mt = 0; mt < 4; mt++) {
#pragma unroll
        for (int nt = 0; nt < 4; nt++) {
            int row = m0 + wm + mt * 16 + (lane >> 2);
            int col = n0 + wn + nt * 8 + 2 * (lane & 3);
            *(float2*)&C[(size_t)row * N + col] =
                make_float2(acc[mt][nt][0], acc[mt][nt][1]);
            *(float2*)&C[(size_t)(row + 8) * N + col] =
                make_float2(acc[mt][nt][2], acc[mt][nt][3]);
        }
    }
}

// ---------------------------------------------------------------------------
// RoPE on Q + K
// ---------------------------------------------------------------------------
__global__ void rope_kernel(const float* __restrict__ cosf,
                            const float* __restrict__ sinf)
{
    const int total = BB * SS * (NH + NKV) * HHALF;
    int idx = blockIdx.x * blockDim.x + threadIdx.x;
    if (idx >= total) return;

    int pair = idx % HHALF;
    int tmp  = idx / HHALF;
    int h    = tmp % (NH + NKV);
    tmp     /= (NH + NKV);
    int s    = tmp % SS;
    int b    = tmp / SS;

    int a;
    if (h < NH) a = (h / QPK) * ((QPK + 2) * HD) + (h % QPK) * HD;
    else        a = (h - NH) * ((QPK + 2) * HD) + QPK * HD;

    float* p = g_qkv + (size_t)(b * SS + s) * ASH + a + 2 * pair;
    float c  = cosf[s * HHALF + pair];
    float sn = sinf[s * HHALF + pair];
    float xr = p[0], xi = p[1];
    p[0] = xr * c - xi * sn;
    p[1] = xr * sn + xi * c;
}

// ---------------------------------------------------------------------------
// Flash attention, bf16x3, GQA-shared K/V:
// CTA = (qb, kv, b), 512 threads / 16 warps. warp>>2 = head-in-group (4 q
// heads share this CTA's K/V tiles), warp&3 = 16-row q slice.
// K/V loaded + bf16-split ONCE per CTA per tile (was 4x).
// ---------------------------------------------------------------------------
#define BP 72
#define TS (64 * BP)
#define FLASH_SMEM (20 * TS * 2)   // 184,320 B

__device__ __forceinline__ void bsplit(float f, __nv_bfloat16& hi, __nv_bfloat16& lo) {
    hi = __float2bfloat16_rn(f);
    lo = __float2bfloat16_rn(f - __bfloat162float(hi));
}

__global__ __launch_bounds__(512) void flash_bf16_gqa()
{
    extern __shared__ __nv_bfloat16 smb[];
    __nv_bfloat16* Kh     = smb;
    __nv_bfloat16* Kl     = Kh  + TS;
    __nv_bfloat16* Vth    = Kl  + TS;       // transposed: rows=d, cols=key
    __nv_bfloat16* Vtl    = Vth + TS;
    __nv_bfloat16* Qh_all = Vtl + TS;       // 4 heads
    __nv_bfloat16* Ql_all = Qh_all + 4 * TS;
    __nv_bfloat16* Ph_all = Ql_all + 4 * TS;
    __nv_bfloat16* Pl_all = Ph_all + 4 * TS;

    const int tid  = threadIdx.x;
    const int lane = tid & 31;
    const int warp = tid >> 5;
    const int qb = blockIdx.x;
    const int kv = blockIdx.y;
    const int b  = blockIdx.z;

    const int hg = warp >> 2;               // head in KV group (0..3)
    const int h  = kv * 4 + hg;
    const int koff = kv * 384 + 256;
    const int voff = kv * 384 + 320;

    __nv_bfloat16* Qh = Qh_all + hg * TS;
    __nv_bfloat16* Ql = Ql_all + hg * TS;
    __nv_bfloat16* Ph = Ph_all + hg * TS;
    __nv_bfloat16* Pl = Pl_all + hg * TS;

    // ---- load + split all 4 heads' Q tiles (cooperative, 512 threads) ----
#pragma unroll
    for (int it = 0; it < 8; ++it) {
        int f = tid + it * 512;             // 0..4095
        int head = f >> 10;                 // 64*16 float4 per head
        int rem  = f & 1023;
        int row  = rem >> 4, c4 = rem & 15;
        const float* src = g_qkv + (size_t)(b * SS + qb * 64 + row) * ASH
                         + kv * 384 + head * 64 + c4 * 4;
        float4 v = *(const float4*)src;
        __nv_bfloat16 h0, l0, h1, l1, h2, l2, h3, l3;
        bsplit(v.x, h0, l0); bsplit(v.y, h1, l1);
        bsplit(v.z, h2, l2); bsplit(v.w, h3, l3);
        int o = head * TS + row * BP + c4 * 4;
        Qh_all[o] = h0; Qh_all[o+1] = h1; Qh_all[o+2] = h2; Qh_all[o+3] = h3;
        Ql_all[o] = l0; Ql_all[o+1] = l1; Ql_all[o+2] = l2; Ql_all[o+3] = l3;
    }

    const int r0  = lane >> 2;
    const int q4  = lane & 3;
    const int w16 = (warp & 3) * 16;
    const int qrow0 = qb * 64 + w16 + r0;
    const int qrow1 = qrow0 + 8;
    const float scale = 0.125f;

    float accO[8][4];
#pragma unroll
    for (int nt = 0; nt < 8; nt++)
#pragma unroll
        for (int r = 0; r < 4; r++) accO[nt][r] = 0.f;

    float mr0 = -1e30f, mr1 = -1e30f;
    float l0s = 0.f, l1s = 0.f;

    for (int kb = 0; kb <= qb; ++kb) {
        __syncthreads();    // prior-tile K/V reads complete (covers Q split on kb=0)
        const float* kvb = g_qkv + (size_t)(b * SS + kb * 64) * ASH;
#pragma unroll
        for (int it = 0; it < 2; ++it) {
            int f = tid + it * 512;         // 0..1023
            int row = f >> 4, c4 = f & 15;
            float4 kk = *(const float4*)(kvb + (size_t)row * ASH + koff + c4 * 4);
            float4 vv = *(const float4*)(kvb + (size_t)row * ASH + voff + c4 * 4);
            __nv_bfloat16 h0, lo0, h1, lo1, h2, lo2, h3, lo3;
            bsplit(kk.x, h0, lo0); bsplit(kk.y, h1, lo1);
            bsplit(kk.z, h2, lo2); bsplit(kk.w, h3, lo3);
            int o = row * BP + c4 * 4;
            Kh[o] = h0;  Kh[o+1] = h1;  Kh[o+2] = h2;  Kh[o+3] = h3;
            Kl[o] = lo0; Kl[o+1] = lo1; Kl[o+2] = lo2; Kl[o+3] = lo3;
            bsplit(vv.x, h0, lo0); bsplit(vv.y, h1, lo1);
            bsplit(vv.z, h2, lo2); bsplit(vv.w, h3, lo3);
            int d0 = c4 * 4;
            Vth[(d0    ) * BP + row] = h0;  Vtl[(d0    ) * BP + row] = lo0;
            Vth[(d0 + 1) * BP + row] = h1;  Vtl[(d0 + 1) * BP + row] = lo1;
            Vth[(d0 + 2) * BP + row] = h2;  Vtl[(d0 + 2) * BP + row] = lo2;
            Vth[(d0 + 3) * BP + row] = h3;  Vtl[(d0 + 3) * BP + row] = lo3;
        }
        __syncthreads();

        // ---- scores: S = Q @ K^T ----
        float accS[8][4];
#pragma unroll
        for (int nt = 0; nt < 8; nt++)
#pragma unroll
            for (int r = 0; r < 4; r++) accS[nt][r] = 0.f;

#pragma unroll
        for (int kc = 0; kc < 4; ++kc) {
            const int kq = kc * 16 + 2 * q4;
            uint32_t qh[4], ql[4];
            qh[0] = *(const uint32_t*)&Qh[(w16 + r0    ) * BP + kq    ];
            qh[1] = *(const uint32_t*)&Qh[(w16 + r0 + 8) * BP + kq    ];
            qh[2] = *(const uint32_t*)&Qh[(w16 + r0    ) * BP + kq + 8];
            qh[3] = *(const uint32_t*)&Qh[(w16 + r0 + 8) * BP + kq + 8];
            ql[0] = *(const uint32_t*)&Ql[(w16 + r0    ) * BP + kq    ];
            ql[1] = *(const uint32_t*)&Ql[(w16 + r0 + 8) * BP + kq    ];
            ql[2] = *(const uint32_t*)&Ql[(w16 + r0    ) * BP + kq + 8];
            ql[3] = *(const uint32_t*)&Ql[(w16 + r0 + 8) * BP + kq + 8];
#pragma unroll
            for (int nt = 0; nt < 8; ++nt) {
                const int rb = (nt * 8 + r0) * BP;
                uint32_t kh[2], kl[2];
                kh[0] = *(const uint32_t*)&Kh[rb + kq    ];
                kh[1] = *(const uint32_t*)&Kh[rb + kq + 8];
                kl[0] = *(const uint32_t*)&Kl[rb + kq    ];
                kl[1] = *(const uint32_t*)&Kl[rb + kq + 8];
                mma16(accS[nt], qh, kh);
                mma16(accS[nt], qh, kl);
                mma16(accS[nt], ql, kh);
            }
        }

        // ---- mask + scale + online softmax ----
        float tmax0 = -1e30f, tmax1 = -1e30f;
#pragma unroll
        for (int nt = 0; nt < 8; ++nt) {
            int kc0 = kb * 64 + nt * 8 + q4 * 2;
#pragma unroll
            for (int c = 0; c < 2; ++c) {
                float s0 = accS[nt][c]     * scale;
                float s1 = accS[nt][c + 2] * scale;
                if (kc0 + c > qrow0) s0 = -1e30f;
                if (kc0 + c > qrow1) s1 = -1e30f;
                accS[nt][c]     = s0;
                accS[nt][c + 2] = s1;
                tmax0 = fmaxf(tmax0, s0);
                tmax1 = fmaxf(tmax1, s1);
            }
        }
        tmax0 = fmaxf(tmax0, __shfl_xor_sync(0xffffffff, tmax0, 1));
        tmax0 = fmaxf(tmax0, __shfl_xor_sync(0xffffffff, tmax0, 2));
        tmax1 = fmaxf(tmax1, __shfl_xor_sync(0xffffffff, tmax1, 1));
        tmax1 = fmaxf(tmax1, __shfl_xor_sync(0xffffffff, tmax1, 2));

        float mn0 = fmaxf(mr0, tmax0);
        float mn1 = fmaxf(mr1, tmax1);
        float al0 = __expf(mr0 - mn0);
        float al1 = __expf(mr1 - mn1);
        mr0 = mn0; mr1 = mn1;

        float ls0 = 0.f, ls1 = 0.f;
#pragma unroll
        for (int nt = 0; nt < 8; ++nt) {
            float p0 = __expf(accS[nt][0] - mn0);
            float p1 = __expf(accS[nt][1] - mn0);
            float p2 = __expf(accS[nt][2] - mn1);
            float p3 = __expf(accS[nt][3] - mn1);
            ls0 += p0 + p1;
            ls1 += p2 + p3;
            int col = nt * 8 + q4 * 2;
            __nv_bfloat16 h0, lo0, h1, lo1;
            bsplit(p0, h0, lo0); bsplit(p1, h1, lo1);
            *(__nv_bfloat162*)&Ph[(w16 + r0) * BP + col] = __nv_bfloat162(h0, h1);
            *(__nv_bfloat162*)&Pl[(w16 + r0) * BP + col] = __nv_bfloat162(lo0, lo1);
            bsplit(p2, h0, lo0); bsplit(p3, h1, lo1);
            *(__nv_bfloat162*)&Ph[(w16 + r0 + 8) * BP + col] = __nv_bfloat162(h0, h1);
            *(__nv_bfloat162*)&Pl[(w16 + r0 + 8) * BP + col] = __nv_bfloat162(lo0, lo1);
        }
        l0s = l0s * al0 + ls0;
        l1s = l1s * al1 + ls1;

#pragma unroll
        for (int nt = 0; nt < 8; ++nt) {
            accO[nt][0] *= al0; accO[nt][1] *= al0;
            accO[nt][2] *= al1; accO[nt][3] *= al1;
        }
        __syncwarp();

        // ---- PV: O += P @ V ----
#pragma unroll
        for (int kc = 0; kc < 4; ++kc) {
            const int kk = kc * 16 + 2 * q4;
            uint32_t ph[4], pl[4];
            ph[0] = *(const uint32_t*)&Ph[(w16 + r0    ) * BP + kk    ];
            ph[1] = *(const uint32_t*)&Ph[(w16 + r0 + 8) * BP + kk    ];
            ph[2] = *(const uint32_t*)&Ph[(w16 + r0    ) * BP + kk + 8];
            ph[3] = *(const uint32_t*)&Ph[(w16 + r0 + 8) * BP + kk + 8];
            pl[0] = *(const uint32_t*)&Pl[(w16 + r0    ) * BP + kk    ];
            pl[1] = *(const uint32_t*)&Pl[(w16 + r0 + 8) * BP + kk    ];
            pl[2] = *(const uint32_t*)&Pl[(w16 + r0    ) * BP + kk + 8];
            pl[3] = *(const uint32_t*)&Pl[(w16 + r0 + 8) * BP + kk + 8];
#pragma unroll
            for (int nt = 0; nt < 8; ++nt) {
                const int rb = (nt * 8 + r0) * BP;   // row = d
                uint32_t vh[2], vl[2];
                vh[0] = *(const uint32_t*)&Vth[rb + kk    ];
                vh[1] = *(const uint32_t*)&Vth[rb + kk + 8];
                vl[0] = *(const uint32_t*)&Vtl[rb + kk    ];
                vl[1] = *(const uint32_t*)&Vtl[rb + kk + 8];
                mma16(accO[nt], ph, vh);
                mma16(accO[nt], ph, vl);
                mma16(accO[nt], pl, vh);
            }
        }
    }

    // ---- finalize (tf32-round o so WO gemm needs no cvt) ----
    l0s += __shfl_xor_sync(0xffffffff, l0s, 1);
    l0s += __shfl_xor_sync(0xffffffff, l0s, 2);
    l1s += __shfl_xor_sync(0xffffffff, l1s, 1);
    l1s += __shfl_xor_sync(0xffffffff, l1s, 2);
    float inv0 = 1.f / l0s;
    float inv1 = 1.f / l1s;

    float* ob0 = g_o + (size_t)(b * SS + qrow0) * DIM + h * HD;
    float* ob1 = g_o + (size_t)(b * SS + qrow1) * DIM + h * HD;
#pragma unroll
    for (int nt = 0; nt < 8; ++nt) {
        int col = nt * 8 + q4 * 2;
        *(float2*)&ob0[col] = make_float2(
            __uint_as_float(f2tf(accO[nt][0] * inv0)),
            __uint_as_float(f2tf(accO[nt][1] * inv0)));
        *(float2*)&ob1[col] = make_float2(
            __uint_as_float(f2tf(accO[nt][2] * inv1)),
            __uint_as_float(f2tf(accO[nt][3] * inv1)));
    }
}

// ---------------------------------------------------------------------------
extern "C" void kernel_launch(void* const* d_in, const int* in_sizes, int n_in,
                              void* d_out, int out_size)
{
    const float* x    = (const float*)d_in[0];
    const float* fc   = (const float*)d_in[1];
    const float* fs   = (const float*)d_in[2];
    const float* wqkv = (const float*)d_in[3];
    const float* wo   = (const float*)d_in[4];
    float* out = (float*)d_out;

    float *qkv, *o, *xr, *wqkvr, *wor;
    cudaGetSymbolAddress((void**)&qkv,   g_qkv);
    cudaGetSymbolAddress((void**)&o,     g_o);
    cudaGetSymbolAddress((void**)&xr,    g_xr);
    cudaGetSymbolAddress((void**)&wqkvr, g_wqkvr);
    cudaGetSymbolAddress((void**)&wor,   g_wor);

    cudaFuncSetAttribute(tf32_gemm_p3, cudaFuncAttributeMaxDynamicSharedMemorySize,
                         GEMM_SMEM);
    cudaFuncSetAttribute(flash_bf16_gqa, cudaFuncAttributeMaxDynamicSharedMemorySize,
                         FLASH_SMEM);

    // 0) tf32-round inputs
    {
        int n4;
        n4 = BB * SS * DIM / 4;
        round_tf32<<<(n4 + 255) / 256, 256>>>(x, xr, n4);
        n4 = ASH * DIM / 4;
        round_tf32<<<(n4 + 255) / 256, 256>>>(wqkv, wqkvr, n4);
        n4 = DIM * DIM / 4;
        round_tf32<<<(n4 + 255) / 256, 256>>>(wo, wor, n4);
    }

    // 1) QKV projection  [tf32 TC, 3-stage pipeline]
    tf32_gemm_p3<<<dim3(ASH / BN, (BB * SS) / BM), 256, GEMM_SMEM>>>(
        xr, wqkvr, qkv, BB * SS, ASH, DIM);

    // 2) RoPE
    int total = BB * SS * (NH + NKV) * HHALF;
    rope_kernel<<<(total + 255) / 256, 256>>>(fc, fs);

    // 3) causal flash attention  [bf16x3 TC, GQA-shared K/V]
    flash_bf16_gqa<<<dim3(SS / 64, NKV, BB), 512, FLASH_SMEM>>>();

    // 4) output projection  [tf32 TC, 3-stage pipeline]
    tf32_gemm_p3<<<dim3(DIM / BN, (BB * SS) / BM), 256, GEMM_SMEM>>>(
        o, wor, out, BB * SS, DIM, DIM);
}

// round 9
// speedup vs baseline: 5.8508x; 1.5296x over previous
#include <cuda_runtime.h>
#include <cuda_bf16.h>
#include <cuda_fp16.h>
#include <cstdint>

#define BB 4
#define SS 1024
#define DIM 2048
#define NH 32
#define NKV 8
#define HD 64
#define QPK 4
#define ASH 3072
#define HHALF 32

// Scratch (device globals — allocation-free per harness rules)
__device__ float  g_qkv[BB * SS * ASH];    // qkv projection (f32, rope+flash input)
__device__ __half g_oh[BB * SS * DIM];     // attention out (fp16, WO gemm A operand)
__device__ __half g_xh[BB * SS * DIM];     // fp16 x
__device__ __half g_wqkvh[ASH * DIM];      // fp16 wqkv
__device__ __half g_woh[DIM * DIM];        // fp16 wo

__device__ __forceinline__ void mma16h(float* c, const uint32_t* a, const uint32_t* b) {
    asm volatile(
        "mma.sync.aligned.m16n8k16.row.col.f32.f16.f16.f32 "
        "{%0,%1,%2,%3}, {%4,%5,%6,%7}, {%8,%9}, {%0,%1,%2,%3};\n"
        : "+f"(c[0]), "+f"(c[1]), "+f"(c[2]), "+f"(c[3])
        : "r"(a[0]), "r"(a[1]), "r"(a[2]), "r"(a[3]), "r"(b[0]), "r"(b[1]));
}

__device__ __forceinline__ void mma16b(float* c, const uint32_t* a, const uint32_t* b) {
    asm volatile(
        "mma.sync.aligned.m16n8k16.row.col.f32.bf16.bf16.f32 "
        "{%0,%1,%2,%3}, {%4,%5,%6,%7}, {%8,%9}, {%0,%1,%2,%3};\n"
        : "+f"(c[0]), "+f"(c[1]), "+f"(c[2]), "+f"(c[3])
        : "r"(a[0]), "r"(a[1]), "r"(a[2]), "r"(a[3]), "r"(b[0]), "r"(b[1]));
}

// ---------------------------------------------------------------------------
// Prepass: f32 -> f16 convert-copy
// ---------------------------------------------------------------------------
__global__ void to_f16(const float* __restrict__ in, __half* __restrict__ out, int n4)
{
    int i = blockIdx.x * blockDim.x + threadIdx.x;
    if (i >= n4) return;
    float4 v = ((const float4*)in)[i];
    __half2 a = __floats2half2_rn(v.x, v.y);
    __half2 b = __floats2half2_rn(v.z, v.w);
    ((__half2*)out)[2 * i]     = a;
    ((__half2*)out)[2 * i + 1] = b;
}

// ---------------------------------------------------------------------------
// FP16 TC GEMM (f32 accumulate): C[M,N] = A[M,K] * B[N,K]^T, both fp16 K-major.
// 128x128 CTA tile, BK=32, 3-stage cp.async, 8 warps @ 64x32, mma m16n8k16.
// ---------------------------------------------------------------------------
#define BM 128
#define BN 128
#define BKH 32
#define HPAD 40     // half pitch: (row*20 + k/2) covers all banks for frag loads
#define GSTAGE 3
#define GEMM_SMEM (GSTAGE * (BM + BN) * HPAD * 2)   // 61,440 B

__device__ __forceinline__ void cp16(void* smem, const void* gmem) {
    uint32_t sa = (uint32_t)__cvta_generic_to_shared(smem);
    asm volatile("cp.async.cg.shared.global [%0], [%1], 16;\n" :: "r"(sa), "l"(gmem));
}

__global__ __launch_bounds__(256) void f16_gemm(
    const __half* __restrict__ A, const __half* __restrict__ Bm,
    float* __restrict__ C, int M, int N, int K)
{
    extern __shared__ __half hsm[];

    const int tid  = threadIdx.x;
    const int lane = tid & 31;
    const int warp = tid >> 5;
    const int wm = (warp >> 2) * 64;
    const int wn = (warp & 3) * 32;
    const int m0 = blockIdx.y * BM;
    const int n0 = blockIdx.x * BN;

    float acc[4][4][4];
#pragma unroll
    for (int mt = 0; mt < 4; mt++)
#pragma unroll
        for (int nt = 0; nt < 4; nt++)
#pragma unroll
            for (int r = 0; r < 4; r++) acc[mt][nt][r] = 0.f;

    const int ntiles = K / BKH;

    auto load_stage = [&](int s, int k0) {
        __half* as = hsm + s * (BM + BN) * HPAD;
        __half* bs = as + BM * HPAD;
#pragma unroll
        for (int it = 0; it < 2; ++it) {
            int f = tid + it * 256;        // 0..511
            int row = f >> 2, ch = (f & 3) * 8;
            cp16(as + row * HPAD + ch, A  + (size_t)(m0 + row) * K + k0 + ch);
            cp16(bs + row * HPAD + ch, Bm + (size_t)(n0 + row) * K + k0 + ch);
        }
        asm volatile("cp.async.commit_group;\n");
    };

    load_stage(0, 0);
    load_stage(1, BKH);

    for (int kt = 0; kt < ntiles; ++kt) {
        if (kt + 1 < ntiles) asm volatile("cp.async.wait_group 1;\n");
        else                 asm volatile("cp.async.wait_group 0;\n");
        __syncthreads();

        if (kt + 2 < ntiles) load_stage((kt + 2) % GSTAGE, (kt + 2) * BKH);

        const __half* as = hsm + (kt % GSTAGE) * (BM + BN) * HPAD;
        const __half* bs = as + BM * HPAD;

#pragma unroll
        for (int ks = 0; ks < BKH; ks += 16) {
            uint32_t af[4][4], bf[4][2];
            const int ar = lane >> 2;
            const int ac = ks + (lane & 3) * 2;
#pragma unroll
            for (int mt = 0; mt < 4; mt++) {
                af[mt][0] = *(const uint32_t*)&as[(wm + mt * 16 + ar    ) * HPAD + ac    ];
                af[mt][1] = *(const uint32_t*)&as[(wm + mt * 16 + ar + 8) * HPAD + ac    ];
                af[mt][2] = *(const uint32_t*)&as[(wm + mt * 16 + ar    ) * HPAD + ac + 8];
                af[mt][3] = *(const uint32_t*)&as[(wm + mt * 16 + ar + 8) * HPAD + ac + 8];
            }
#pragma unroll
            for (int nt = 0; nt < 4; nt++) {
                bf[nt][0] = *(const uint32_t*)&bs[(wn + nt * 8 + ar) * HPAD + ac    ];
                bf[nt][1] = *(const uint32_t*)&bs[(wn + nt * 8 + ar) * HPAD + ac + 8];
            }
#pragma unroll
            for (int mt = 0; mt < 4; mt++)
#pragma unroll
                for (int nt = 0; nt < 4; nt++)
                    mma16h(acc[mt][nt], af[mt], bf[nt]);
        }
        __syncthreads();
    }

#pragma unroll
    for (int mt = 0; mt < 4; mt++) {
#pragma unroll
        for (int nt = 0; nt < 4; nt++) {
            int row = m0 + wm + mt * 16 + (lane >> 2);
            int col = n0 + wn + nt * 8 + 2 * (lane & 3);
            *(float2*)&C[(size_t)row * N + col] =
                make_float2(acc[mt][nt][0], acc[mt][nt][1]);
            *(float2*)&C[(size_t)(row + 8) * N + col] =
                make_float2(acc[mt][nt][2], acc[mt][nt][3]);
        }
    }
}

// ---------------------------------------------------------------------------
// RoPE on Q + K (f32, in-place on g_qkv)
// ---------------------------------------------------------------------------
__global__ void rope_kernel(const float* __restrict__ cosf,
                            const float* __restrict__ sinf)
{
    const int total = BB * SS * (NH + NKV) * HHALF;
    int idx = blockIdx.x * blockDim.x + threadIdx.x;
    if (idx >= total) return;

    int pair = idx % HHALF;
    int tmp  = idx / HHALF;
    int h    = tmp % (NH + NKV);
    tmp     /= (NH + NKV);
    int s    = tmp % SS;
    int b    = tmp / SS;

    int a;
    if (h < NH) a = (h / QPK) * ((QPK + 2) * HD) + (h % QPK) * HD;
    else        a = (h - NH) * ((QPK + 2) * HD) + QPK * HD;

    float* p = g_qkv + (size_t)(b * SS + s) * ASH + a + 2 * pair;
    float c  = cosf[s * HHALF + pair];
    float sn = sinf[s * HHALF + pair];
    float xr = p[0], xi = p[1];
    p[0] = xr * c - xi * sn;
    p[1] = xr * sn + xi * c;
}

// ---------------------------------------------------------------------------
// Flash attention, bf16x3, GQA-shared K/V (proven R6 design).
// Epilogue writes fp16 directly for the WO gemm.
// ---------------------------------------------------------------------------
#define BP 72
#define TS (64 * BP)
#define FLASH_SMEM (20 * TS * 2)   // 184,320 B

__device__ __forceinline__ void bsplit(float f, __nv_bfloat16& hi, __nv_bfloat16& lo) {
    hi = __float2bfloat16_rn(f);
    lo = __float2bfloat16_rn(f - __bfloat162float(hi));
}

__global__ __launch_bounds__(512) void flash_bf16_gqa()
{
    extern __shared__ __nv_bfloat16 smb[];
    __nv_bfloat16* Kh     = smb;
    __nv_bfloat16* Kl     = Kh  + TS;
    __nv_bfloat16* Vth    = Kl  + TS;       // transposed: rows=d, cols=key
    __nv_bfloat16* Vtl    = Vth + TS;
    __nv_bfloat16* Qh_all = Vtl + TS;
    __nv_bfloat16* Ql_all = Qh_all + 4 * TS;
    __nv_bfloat16* Ph_all = Ql_all + 4 * TS;
    __nv_bfloat16* Pl_all = Ph_all + 4 * TS;

    const int tid  = threadIdx.x;
    const int lane = tid & 31;
    const int warp = tid >> 5;
    const int qb = blockIdx.x;
    const int kv = blockIdx.y;
    const int b  = blockIdx.z;

    const int hg = warp >> 2;
    const int h  = kv * 4 + hg;
    const int koff = kv * 384 + 256;
    const int voff = kv * 384 + 320;

    __nv_bfloat16* Qh = Qh_all + hg * TS;
    __nv_bfloat16* Ql = Ql_all + hg * TS;
    __nv_bfloat16* Ph = Ph_all + hg * TS;
    __nv_bfloat16* Pl = Pl_all + hg * TS;

    // ---- load + split all 4 heads' Q tiles ----
#pragma unroll
    for (int it = 0; it < 8; ++it) {
        int f = tid + it * 512;
        int head = f >> 10;
        int rem  = f & 1023;
        int row  = rem >> 4, c4 = rem & 15;
        const float* src = g_qkv + (size_t)(b * SS + qb * 64 + row) * ASH
                         + kv * 384 + head * 64 + c4 * 4;
        float4 v = *(const float4*)src;
        __nv_bfloat16 h0, l0, h1, l1, h2, l2, h3, l3;
        bsplit(v.x, h0, l0); bsplit(v.y, h1, l1);
        bsplit(v.z, h2, l2); bsplit(v.w, h3, l3);
        int o = head * TS + row * BP + c4 * 4;
        Qh_all[o] = h0; Qh_all[o+1] = h1; Qh_all[o+2] = h2; Qh_all[o+3] = h3;
        Ql_all[o] = l0; Ql_all[o+1] = l1; Ql_all[o+2] = l2; Ql_all[o+3] = l3;
    }

    const int r0  = lane >> 2;
    const int q4  = lane & 3;
    const int w16 = (warp & 3) * 16;
    const int qrow0 = qb * 64 + w16 + r0;
    const int qrow1 = qrow0 + 8;
    const float scale = 0.125f;

    float accO[8][4];
#pragma unroll
    for (int nt = 0; nt < 8; nt++)
#pragma unroll
        for (int r = 0; r < 4; r++) accO[nt][r] = 0.f;

    float mr0 = -1e30f, mr1 = -1e30f;
    float l0s = 0.f, l1s = 0.f;

    for (int kb = 0; kb <= qb; ++kb) {
        __syncthreads();
        const float* kvb = g_qkv + (size_t)(b * SS + kb * 64) * ASH;
#pragma unroll
        for (int it = 0; it < 2; ++it) {
            int f = tid + it * 512;
            int row = f >> 4, c4 = f & 15;
            float4 kk = *(const float4*)(kvb + (size_t)row * ASH + koff + c4 * 4);
            float4 vv = *(const float4*)(kvb + (size_t)row * ASH + voff + c4 * 4);
            __nv_bfloat16 h0, lo0, h1, lo1, h2, lo2, h3, lo3;
            bsplit(kk.x, h0, lo0); bsplit(kk.y, h1, lo1);
            bsplit(kk.z, h2, lo2); bsplit(kk.w, h3, lo3);
            int o = row * BP + c4 * 4;
            Kh[o] = h0;  Kh[o+1] = h1;  Kh[o+2] = h2;  Kh[o+3] = h3;
            Kl[o] = lo0; Kl[o+1] = lo1; Kl[o+2] = lo2; Kl[o+3] = lo3;
            bsplit(vv.x, h0, lo0); bsplit(vv.y, h1, lo1);
            bsplit(vv.z, h2, lo2); bsplit(vv.w, h3, lo3);
            int d0 = c4 * 4;
            Vth[(d0    ) * BP + row] = h0;  Vtl[(d0    ) * BP + row] = lo0;
            Vth[(d0 + 1) * BP + row] = h1;  Vtl[(d0 + 1) * BP + row] = lo1;
            Vth[(d0 + 2) * BP + row] = h2;  Vtl[(d0 + 2) * BP + row] = lo2;
            Vth[(d0 + 3) * BP + row] = h3;  Vtl[(d0 + 3) * BP + row] = lo3;
        }
        __syncthreads();

        // ---- scores ----
        float accS[8][4];
#pragma unroll
        for (int nt = 0; nt < 8; nt++)
#pragma unroll
            for (int r = 0; r < 4; r++) accS[nt][r] = 0.f;

#pragma unroll
        for (int kc = 0; kc < 4; ++kc) {
            const int kq = kc * 16 + 2 * q4;
            uint32_t qh[4], ql[4];
            qh[0] = *(const uint32_t*)&Qh[(w16 + r0    ) * BP + kq    ];
            qh[1] = *(const uint32_t*)&Qh[(w16 + r0 + 8) * BP + kq    ];
            qh[2] = *(const uint32_t*)&Qh[(w16 + r0    ) * BP + kq + 8];
            qh[3] = *(const uint32_t*)&Qh[(w16 + r0 + 8) * BP + kq + 8];
            ql[0] = *(const uint32_t*)&Ql[(w16 + r0    ) * BP + kq    ];
            ql[1] = *(const uint32_t*)&Ql[(w16 + r0 + 8) * BP + kq    ];
            ql[2] = *(const uint32_t*)&Ql[(w16 + r0    ) * BP + kq + 8];
            ql[3] = *(const uint32_t*)&Ql[(w16 + r0 + 8) * BP + kq + 8];
#pragma unroll
            for (int nt = 0; nt < 8; ++nt) {
                const int rb = (nt * 8 + r0) * BP;
                uint32_t kh[2], kl[2];
                kh[0] = *(const uint32_t*)&Kh[rb + kq    ];
                kh[1] = *(const uint32_t*)&Kh[rb + kq + 8];
                kl[0] = *(const uint32_t*)&Kl[rb + kq    ];
                kl[1] = *(const uint32_t*)&Kl[rb + kq + 8];
                mma16b(accS[nt], qh, kh);
                mma16b(accS[nt], qh, kl);
                mma16b(accS[nt], ql, kh);
            }
        }

        // ---- mask + scale + online softmax ----
        float tmax0 = -1e30f, tmax1 = -1e30f;
#pragma unroll
        for (int nt = 0; nt < 8; ++nt) {
            int kc0 = kb * 64 + nt * 8 + q4 * 2;
#pragma unroll
            for (int c = 0; c < 2; ++c) {
                float s0 = accS[nt][c]     * scale;
                float s1 = accS[nt][c + 2] * scale;
                if (kc0 + c > qrow0) s0 = -1e30f;
                if (kc0 + c > qrow1) s1 = -1e30f;
                accS[nt][c]     = s0;
                accS[nt][c + 2] = s1;
                tmax0 = fmaxf(tmax0, s0);
                tmax1 = fmaxf(tmax1, s1);
            }
        }
        tmax0 = fmaxf(tmax0, __shfl_xor_sync(0xffffffff, tmax0, 1));
        tmax0 = fmaxf(tmax0, __shfl_xor_sync(0xffffffff, tmax0, 2));
        tmax1 = fmaxf(tmax1, __shfl_xor_sync(0xffffffff, tmax1, 1));
        tmax1 = fmaxf(tmax1, __shfl_xor_sync(0xffffffff, tmax1, 2));

        float mn0 = fmaxf(mr0, tmax0);
        float mn1 = fmaxf(mr1, tmax1);
        float al0 = __expf(mr0 - mn0);
        float al1 = __expf(mr1 - mn1);
        mr0 = mn0; mr1 = mn1;

        float ls0 = 0.f, ls1 = 0.f;
#pragma unroll
        for (int nt = 0; nt < 8; ++nt) {
            float p0 = __expf(accS[nt][0] - mn0);
            float p1 = __expf(accS[nt][1] - mn0);
            float p2 = __expf(accS[nt][2] - mn1);
            float p3 = __expf(accS[nt][3] - mn1);
            ls0 += p0 + p1;
            ls1 += p2 + p3;
            int col = nt * 8 + q4 * 2;
            __nv_bfloat16 h0, lo0, h1, lo1;
            bsplit(p0, h0, lo0); bsplit(p1, h1, lo1);
            *(__nv_bfloat162*)&Ph[(w16 + r0) * BP + col] = __nv_bfloat162(h0, h1);
            *(__nv_bfloat162*)&Pl[(w16 + r0) * BP + col] = __nv_bfloat162(lo0, lo1);
            bsplit(p2, h0, lo0); bsplit(p3, h1, lo1);
            *(__nv_bfloat162*)&Ph[(w16 + r0 + 8) * BP + col] = __nv_bfloat162(h0, h1);
            *(__nv_bfloat162*)&Pl[(w16 + r0 + 8) * BP + col] = __nv_bfloat162(lo0, lo1);
        }
        l0s = l0s * al0 + ls0;
        l1s = l1s * al1 + ls1;

#pragma unroll
        for (int nt = 0; nt < 8; ++nt) {
            accO[nt][0] *= al0; accO[nt][1] *= al0;
            accO[nt][2] *= al1; accO[nt][3] *= al1;
        }
        __syncwarp();

        // ---- PV ----
#pragma unroll
        for (int kc = 0; kc < 4; ++kc) {
            const int kk = kc * 16 + 2 * q4;
            uint32_t ph[4], pl[4];
            ph[0] = *(const uint32_t*)&Ph[(w16 + r0    ) * BP + kk    ];
            ph[1] = *(const uint32_t*)&Ph[(w16 + r0 + 8) * BP + kk    ];
            ph[2] = *(const uint32_t*)&Ph[(w16 + r0    ) * BP + kk + 8];
            ph[3] = *(const uint32_t*)&Ph[(w16 + r0 + 8) * BP + kk + 8];
            pl[0] = *(const uint32_t*)&Pl[(w16 + r0    ) * BP + kk    ];
            pl[1] = *(const uint32_t*)&Pl[(w16 + r0 + 8) * BP + kk    ];
            pl[2] = *(const uint32_t*)&Pl[(w16 + r0    ) * BP + kk + 8];
            pl[3] = *(const uint32_t*)&Pl[(w16 + r0 + 8) * BP + kk + 8];
#pragma unroll
            for (int nt = 0; nt < 8; ++nt) {
                const int rb = (nt * 8 + r0) * BP;
                uint32_t vh[2], vl[2];
                vh[0] = *(const uint32_t*)&Vth[rb + kk    ];
                vh[1] = *(const uint32_t*)&Vth[rb + kk + 8];
                vl[0] = *(const uint32_t*)&Vtl[rb + kk    ];
                vl[1] = *(const uint32_t*)&Vtl[rb + kk + 8];
                mma16b(accO[nt], ph, vh);
                mma16b(accO[nt], ph, vl);
                mma16b(accO[nt], pl, vh);
            }
        }
    }

    // ---- finalize: write fp16 for WO gemm ----
    l0s += __shfl_xor_sync(0xffffffff, l0s, 1);
    l0s += __shfl_xor_sync(0xffffffff, l0s, 2);
    l1s += __shfl_xor_sync(0xffffffff, l1s, 1);
    l1s += __shfl_xor_sync(0xffffffff, l1s, 2);
    float inv0 = 1.f / l0s;
    float inv1 = 1.f / l1s;

    __half* ob0 = g_oh + (size_t)(b * SS + qrow0) * DIM + h * HD;
    __half* ob1 = g_oh + (size_t)(b * SS + qrow1) * DIM + h * HD;
#pragma unroll
    for (int nt = 0; nt < 8; ++nt) {
        int col = nt * 8 + q4 * 2;
        *(__half2*)&ob0[col] = __floats2half2_rn(accO[nt][0] * inv0, accO[nt][1] * inv0);
        *(__half2*)&ob1[col] = __floats2half2_rn(accO[nt][2] * inv1, accO[nt][3] * inv1);
    }
}

// ---------------------------------------------------------------------------
extern "C" void kernel_launch(void* const* d_in, const int* in_sizes, int n_in,
                              void* d_out, int out_size)
{
    const float* x    = (const float*)d_in[0];
    const float* fc   = (const float*)d_in[1];
    const float* fs   = (const float*)d_in[2];
    const float* wqkv = (const float*)d_in[3];
    const float* wo   = (const float*)d_in[4];
    float* out = (float*)d_out;

    float  *qkv;
    __half *oh, *xh, *wqkvh, *woh;
    cudaGetSymbolAddress((void**)&qkv,   g_qkv);
    cudaGetSymbolAddress((void**)&oh,    g_oh);
    cudaGetSymbolAddress((void**)&xh,    g_xh);
    cudaGetSymbolAddress((void**)&wqkvh, g_wqkvh);
    cudaGetSymbolAddress((void**)&woh,   g_woh);

    cudaFuncSetAttribute(f16_gemm, cudaFuncAttributeMaxDynamicSharedMemorySize,
                         GEMM_SMEM);
    cudaFuncSetAttribute(flash_bf16_gqa, cudaFuncAttributeMaxDynamicSharedMemorySize,
                         FLASH_SMEM);

    // 0) fp16 convert inputs
    {
        int n4;
        n4 = BB * SS * DIM / 4;
        to_f16<<<(n4 + 255) / 256, 256>>>(x, xh, n4);
        n4 = ASH * DIM / 4;
        to_f16<<<(n4 + 255) / 256, 256>>>(wqkv, wqkvh, n4);
        n4 = DIM * DIM / 4;
        to_f16<<<(n4 + 255) / 256, 256>>>(wo, woh, n4);
    }

    // 1) QKV projection  [fp16 TC, f32 accum]
    f16_gemm<<<dim3(ASH / BN, (BB * SS) / BM), 256, GEMM_SMEM>>>(
        xh, wqkvh, qkv, BB * SS, ASH, DIM);

    // 2) RoPE
    int total = BB * SS * (NH + NKV) * HHALF;
    rope_kernel<<<(total + 255) / 256, 256>>>(fc, fs);

    // 3) causal flash attention  [bf16x3 TC, GQA-shared K/V]
    flash_bf16_gqa<<<dim3(SS / 64, NKV, BB), 512, FLASH_SMEM>>>();

    // 4) output projection  [fp16 TC, f32 accum]
    f16_gemm<<<dim3(DIM / BN, (BB * SS) / BM), 256, GEMM_SMEM>>>(
        oh, woh, out, BB * SS, DIM, DIM);
}

// round 12
// speedup vs baseline: 6.3639x; 1.0877x over previous
#include <cuda_runtime.h>
#include <cuda_bf16.h>
#include <cuda_fp16.h>
#include <cstdint>

#define BB 4
#define SS 1024
#define DIM 2048
#define NH 32
#define NKV 8
#define HD 64
#define QPK 4
#define ASH 3072
#define HHALF 32

// Scratch (device globals — allocation-free per harness rules)
__device__ float  g_qkv[BB * SS * ASH];    // qkv projection (f32, rope+flash input)
__device__ __half g_oh[BB * SS * DIM];     // attention out (fp16, WO gemm A operand)
__device__ __half g_xh[BB * SS * DIM];     // fp16 x
__device__ __half g_wqkvh[ASH * DIM];      // fp16 wqkv
__device__ __half g_woh[DIM * DIM];        // fp16 wo

__device__ __forceinline__ void mma16h(float* c, const uint32_t* a, const uint32_t* b) {
    asm volatile(
        "mma.sync.aligned.m16n8k16.row.col.f32.f16.f16.f32 "
        "{%0,%1,%2,%3}, {%4,%5,%6,%7}, {%8,%9}, {%0,%1,%2,%3};\n"
        : "+f"(c[0]), "+f"(c[1]), "+f"(c[2]), "+f"(c[3])
        : "r"(a[0]), "r"(a[1]), "r"(a[2]), "r"(a[3]), "r"(b[0]), "r"(b[1]));
}

__device__ __forceinline__ void mma16b(float* c, const uint32_t* a, const uint32_t* b) {
    asm volatile(
        "mma.sync.aligned.m16n8k16.row.col.f32.bf16.bf16.f32 "
        "{%0,%1,%2,%3}, {%4,%5,%6,%7}, {%8,%9}, {%0,%1,%2,%3};\n"
        : "+f"(c[0]), "+f"(c[1]), "+f"(c[2]), "+f"(c[3])
        : "r"(a[0]), "r"(a[1]), "r"(a[2]), "r"(a[3]), "r"(b[0]), "r"(b[1]));
}

__device__ __forceinline__ void ldsm_x4(uint32_t* r, uint32_t addr) {
    asm volatile("ldmatrix.sync.aligned.m8n8.x4.shared.b16 {%0,%1,%2,%3}, [%4];"
                 : "=r"(r[0]), "=r"(r[1]), "=r"(r[2]), "=r"(r[3]) : "r"(addr));
}

// ---------------------------------------------------------------------------
// Prepass: f32 -> f16 convert-copy
// ---------------------------------------------------------------------------
__global__ void to_f16(const float* __restrict__ in, __half* __restrict__ out, int n4)
{
    int i = blockIdx.x * blockDim.x + threadIdx.x;
    if (i >= n4) return;
    float4 v = ((const float4*)in)[i];
    ((__half2*)out)[2 * i]     = __floats2half2_rn(v.x, v.y);
    ((__half2*)out)[2 * i + 1] = __floats2half2_rn(v.z, v.w);
}

// ---------------------------------------------------------------------------
// FP16 TC GEMM (f32 accumulate): C[M,N] = A[M,K] * B[N,K]^T, both fp16 K-major.
// 128x128 CTA tile, BK=32, 3-stage cp.async, 8 warps @ 64x32, mma m16n8k16.
// Fragment loads via ldmatrix.x4 (6 LDSM per 16 HMMA, conflict-free @ HPAD=40).
// ---------------------------------------------------------------------------
#define BM 128
#define BN 128
#define BKH 32
#define HPAD 40
#define GSTAGE 3
#define GEMM_SMEM (GSTAGE * (BM + BN) * HPAD * 2)   // 61,440 B

__device__ __forceinline__ void cp16(void* smem, const void* gmem) {
    uint32_t sa = (uint32_t)__cvta_generic_to_shared(smem);
    asm volatile("cp.async.cg.shared.global [%0], [%1], 16;\n" :: "r"(sa), "l"(gmem));
}

__global__ __launch_bounds__(256) void f16_gemm(
    const __half* __restrict__ A, const __half* __restrict__ Bm,
    float* __restrict__ C, int M, int N, int K)
{
    extern __shared__ __half hsm[];

    const int tid  = threadIdx.x;
    const int lane = tid & 31;
    const int warp = tid >> 5;
    const int wm = (warp >> 2) * 64;
    const int wn = (warp & 3) * 32;
    const int m0 = blockIdx.y * BM;
    const int n0 = blockIdx.x * BN;

    float acc[4][4][4];
#pragma unroll
    for (int mt = 0; mt < 4; mt++)
#pragma unroll
        for (int nt = 0; nt < 4; nt++)
#pragma unroll
            for (int r = 0; r < 4; r++) acc[mt][nt][r] = 0.f;

    const int ntiles = K / BKH;

    auto load_stage = [&](int s, int k0) {
        __half* as = hsm + s * (BM + BN) * HPAD;
        __half* bs = as + BM * HPAD;
#pragma unroll
        for (int it = 0; it < 2; ++it) {
            int f = tid + it * 256;        // 0..511
            int row = f >> 2, ch = (f & 3) * 8;
            cp16(as + row * HPAD + ch, A  + (size_t)(m0 + row) * K + k0 + ch);
            cp16(bs + row * HPAD + ch, Bm + (size_t)(n0 + row) * K + k0 + ch);
        }
        asm volatile("cp.async.commit_group;\n");
    };

    load_stage(0, 0);
    load_stage(1, BKH);

    // ldmatrix lane->address mapping (within a 16-row x 16-k block)
    const int l8 = lane & 7;
    const int a_row = ((lane >> 3) & 1) * 8 + l8;   // A: m offset
    const int a_k   = (lane >> 4) * 8;              // A: k offset
    const int b_row = (lane >> 4) * 8 + l8;         // B: n offset (pair of n8 frags)
    const int b_k   = ((lane >> 3) & 1) * 8;        // B: k offset

    const uint32_t smem0 = (uint32_t)__cvta_generic_to_shared(hsm);

    for (int kt = 0; kt < ntiles; ++kt) {
        if (kt + 1 < ntiles) asm volatile("cp.async.wait_group 1;\n");
        else                 asm volatile("cp.async.wait_group 0;\n");
        __syncthreads();

        if (kt + 2 < ntiles) load_stage((kt + 2) % GSTAGE, (kt + 2) * BKH);

        const uint32_t as = smem0 + (kt % GSTAGE) * (BM + BN) * HPAD * 2;
        const uint32_t bs = as + BM * HPAD * 2;
        const uint32_t abase = as + ((wm + a_row) * HPAD + a_k) * 2;
        const uint32_t bbase = bs + ((wn + b_row) * HPAD + b_k) * 2;

#pragma unroll
        for (int ks = 0; ks < BKH; ks += 16) {
            uint32_t af[4][4], bf[2][4];
#pragma unroll
            for (int mt = 0; mt < 4; mt++)
                ldsm_x4(af[mt], abase + (mt * 16 * HPAD + ks) * 2);
#pragma unroll
            for (int p = 0; p < 2; p++)
                ldsm_x4(bf[p], bbase + (p * 16 * HPAD + ks) * 2);
#pragma unroll
            for (int mt = 0; mt < 4; mt++)
#pragma unroll
                for (int nt = 0; nt < 4; nt++)
                    mma16h(acc[mt][nt], af[mt], &bf[nt >> 1][(nt & 1) * 2]);
        }
        __syncthreads();
    }

#pragma unroll
    for (int mt = 0; mt < 4; mt++) {
#pragma unroll
        for (int nt = 0; nt < 4; nt++) {
            int row = m0 + wm + mt * 16 + (lane >> 2);
            int col = n0 + wn + nt * 8 + 2 * (lane & 3);
            *(float2*)&C[(size_t)row * N + col] =
                make_float2(acc[mt][nt][0], acc[mt][nt][1]);
            *(float2*)&C[(size_t)(row + 8) * N + col] =
                make_float2(acc[mt][nt][2], acc[mt][nt][3]);
        }
    }
}

// ---------------------------------------------------------------------------
// RoPE on Q + K (f32, in-place on g_qkv)
// ---------------------------------------------------------------------------
__global__ void rope_kernel(const float* __restrict__ cosf,
                            const float* __restrict__ sinf)
{
    const int total = BB * SS * (NH + NKV) * HHALF;
    int idx = blockIdx.x * blockDim.x + threadIdx.x;
    if (idx >= total) return;

    int pair = idx % HHALF;
    int tmp  = idx / HHALF;
    int h    = tmp % (NH + NKV);
    tmp     /= (NH + NKV);
    int s    = tmp % SS;
    int b    = tmp / SS;

    int a;
    if (h < NH) a = (h / QPK) * ((QPK + 2) * HD) + (h % QPK) * HD;
    else        a = (h - NH) * ((QPK + 2) * HD) + QPK * HD;

    float* p = g_qkv + (size_t)(b * SS + s) * ASH + a + 2 * pair;
    float c  = cosf[s * HHALF + pair];
    float sn = sinf[s * HHALF + pair];
    float xr = p[0], xi = p[1];
    p[0] = xr * c - xi * sn;
    p[1] = xr * sn + xi * c;
}

// ---------------------------------------------------------------------------
// Flash attention, bf16x3, GQA-shared K/V (proven R6/R9 design).
// Epilogue writes fp16 directly for the WO gemm.
// ---------------------------------------------------------------------------
#define BP 72
#define TS (64 * BP)
#define FLASH_SMEM (20 * TS * 2)   // 184,320 B

__device__ __forceinline__ void bsplit(float f, __nv_bfloat16& hi, __nv_bfloat16& lo) {
    hi = __float2bfloat16_rn(f);
    lo = __float2bfloat16_rn(f - __bfloat162float(hi));
}

__global__ __launch_bounds__(512) void flash_bf16_gqa()
{
    extern __shared__ __nv_bfloat16 smb[];
    __nv_bfloat16* Kh     = smb;
    __nv_bfloat16* Kl     = Kh  + TS;
    __nv_bfloat16* Vth    = Kl  + TS;
    __nv_bfloat16* Vtl    = Vth + TS;
    __nv_bfloat16* Qh_all = Vtl + TS;
    __nv_bfloat16* Ql_all = Qh_all + 4 * TS;
    __nv_bfloat16* Ph_all = Ql_all + 4 * TS;
    __nv_bfloat16* Pl_all = Ph_all + 4 * TS;

    const int tid  = threadIdx.x;
    const int lane = tid & 31;
    const int warp = tid >> 5;
    const int qb = blockIdx.x;
    const int kv = blockIdx.y;
    const int b  = blockIdx.z;

    const int hg = warp >> 2;
    const int h  = kv * 4 + hg;
    const int koff = kv * 384 + 256;
    const int voff = kv * 384 + 320;

    __nv_bfloat16* Qh = Qh_all + hg * TS;
    __nv_bfloat16* Ql = Ql_all + hg * TS;
    __nv_bfloat16* Ph = Ph_all + hg * TS;
    __nv_bfloat16* Pl = Pl_all + hg * TS;

#pragma unroll
    for (int it = 0; it < 8; ++it) {
        int f = tid + it * 512;
        int head = f >> 10;
        int rem  = f & 1023;
        int row  = rem >> 4, c4 = rem & 15;
        const float* src = g_qkv + (size_t)(b * SS + qb * 64 + row) * ASH
                         + kv * 384 + head * 64 + c4 * 4;
        float4 v = *(const float4*)src;
        __nv_bfloat16 h0, l0, h1, l1, h2, l2, h3, l3;
        bsplit(v.x, h0, l0); bsplit(v.y, h1, l1);
        bsplit(v.z, h2, l2); bsplit(v.w, h3, l3);
        int o = head * TS + row * BP + c4 * 4;
        Qh_all[o] = h0; Qh_all[o+1] = h1; Qh_all[o+2] = h2; Qh_all[o+3] = h3;
        Ql_all[o] = l0; Ql_all[o+1] = l1; Ql_all[o+2] = l2; Ql_all[o+3] = l3;
    }

    const int r0  = lane >> 2;
    const int q4  = lane & 3;
    const int w16 = (warp & 3) * 16;
    const int qrow0 = qb * 64 + w16 + r0;
    const int qrow1 = qrow0 + 8;
    const float scale = 0.125f;

    float accO[8][4];
#pragma unroll
    for (int nt = 0; nt < 8; nt++)
#pragma unroll
        for (int r = 0; r < 4; r++) accO[nt][r] = 0.f;

    float mr0 = -1e30f, mr1 = -1e30f;
    float l0s = 0.f, l1s = 0.f;

    for (int kb = 0; kb <= qb; ++kb) {
        __syncthreads();
        const float* kvb = g_qkv + (size_t)(b * SS + kb * 64) * ASH;
#pragma unroll
        for (int it = 0; it < 2; ++it) {
            int f = tid + it * 512;
            int row = f >> 4, c4 = f & 15;
            float4 kk = *(const float4*)(kvb + (size_t)row * ASH + koff + c4 * 4);
            float4 vv = *(const float4*)(kvb + (size_t)row * ASH + voff + c4 * 4);
            __nv_bfloat16 h0, lo0, h1, lo1, h2, lo2, h3, lo3;
            bsplit(kk.x, h0, lo0); bsplit(kk.y, h1, lo1);
            bsplit(kk.z, h2, lo2); bsplit(kk.w, h3, lo3);
            int o = row * BP + c4 * 4;
            Kh[o] = h0;  Kh[o+1] = h1;  Kh[o+2] = h2;  Kh[o+3] = h3;
            Kl[o] = lo0; Kl[o+1] = lo1; Kl[o+2] = lo2; Kl[o+3] = lo3;
            bsplit(vv.x, h0, lo0); bsplit(vv.y, h1, lo1);
            bsplit(vv.z, h2, lo2); bsplit(vv.w, h3, lo3);
            int d0 = c4 * 4;
            Vth[(d0    ) * BP + row] = h0;  Vtl[(d0    ) * BP + row] = lo0;
            Vth[(d0 + 1) * BP + row] = h1;  Vtl[(d0 + 1) * BP + row] = lo1;
            Vth[(d0 + 2) * BP + row] = h2;  Vtl[(d0 + 2) * BP + row] = lo2;
            Vth[(d0 + 3) * BP + row] = h3;  Vtl[(d0 + 3) * BP + row] = lo3;
        }
        __syncthreads();

        float accS[8][4];
#pragma unroll
        for (int nt = 0; nt < 8; nt++)
#pragma unroll
            for (int r = 0; r < 4; r++) accS[nt][r] = 0.f;

#pragma unroll
        for (int kc = 0; kc < 4; ++kc) {
            const int kq = kc * 16 + 2 * q4;
            uint32_t qh[4], ql[4];
            qh[0] = *(const uint32_t*)&Qh[(w16 + r0    ) * BP + kq    ];
            qh[1] = *(const uint32_t*)&Qh[(w16 + r0 + 8) * BP + kq    ];
            qh[2] = *(const uint32_t*)&Qh[(w16 + r0    ) * BP + kq + 8];
            qh[3] = *(const uint32_t*)&Qh[(w16 + r0 + 8) * BP + kq + 8];
            ql[0] = *(const uint32_t*)&Ql[(w16 + r0    ) * BP + kq    ];
            ql[1] = *(const uint32_t*)&Ql[(w16 + r0 + 8) * BP + kq    ];
            ql[2] = *(const uint32_t*)&Ql[(w16 + r0    ) * BP + kq + 8];
            ql[3] = *(const uint32_t*)&Ql[(w16 + r0 + 8) * BP + kq + 8];
#pragma unroll
            for (int nt = 0; nt < 8; ++nt) {
                const int rb = (nt * 8 + r0) * BP;
                uint32_t kh[2], kl[2];
                kh[0] = *(const uint32_t*)&Kh[rb + kq    ];
                kh[1] = *(const uint32_t*)&Kh[rb + kq + 8];
                kl[0] = *(const uint32_t*)&Kl[rb + kq    ];
                kl[1] = *(const uint32_t*)&Kl[rb + kq + 8];
                mma16b(accS[nt], qh, kh);
                mma16b(accS[nt], qh, kl);
                mma16b(accS[nt], ql, kh);
            }
        }

        float tmax0 = -1e30f, tmax1 = -1e30f;
#pragma unroll
        for (int nt = 0; nt < 8; ++nt) {
            int kc0 = kb * 64 + nt * 8 + q4 * 2;
#pragma unroll
            for (int c = 0; c < 2; ++c) {
                float s0 = accS[nt][c]     * scale;
                float s1 = accS[nt][c + 2] * scale;
                if (kc0 + c > qrow0) s0 = -1e30f;
                if (kc0 + c > qrow1) s1 = -1e30f;
                accS[nt][c]     = s0;
                accS[nt][c + 2] = s1;
                tmax0 = fmaxf(tmax0, s0);
                tmax1 = fmaxf(tmax1, s1);
            }
        }
        tmax0 = fmaxf(tmax0, __shfl_xor_sync(0xffffffff, tmax0, 1));
        tmax0 = fmaxf(tmax0, __shfl_xor_sync(0xffffffff, tmax0, 2));
        tmax1 = fmaxf(tmax1, __shfl_xor_sync(0xffffffff, tmax1, 1));
        tmax1 = fmaxf(tmax1, __shfl_xor_sync(0xffffffff, tmax1, 2));

        float mn0 = fmaxf(mr0, tmax0);
        float mn1 = fmaxf(mr1, tmax1);
        float al0 = __expf(mr0 - mn0);
        float al1 = __expf(mr1 - mn1);
        mr0 = mn0; mr1 = mn1;

        float ls0 = 0.f, ls1 = 0.f;
#pragma unroll
        for (int nt = 0; nt < 8; ++nt) {
            float p0 = __expf(accS[nt][0] - mn0);
            float p1 = __expf(accS[nt][1] - mn0);
            float p2 = __expf(accS[nt][2] - mn1);
            float p3 = __expf(accS[nt][3] - mn1);
            ls0 += p0 + p1;
            ls1 += p2 + p3;
            int col = nt * 8 + q4 * 2;
            __nv_bfloat16 h0, lo0, h1, lo1;
            bsplit(p0, h0, lo0); bsplit(p1, h1, lo1);
            *(__nv_bfloat162*)&Ph[(w16 + r0) * BP + col] = __nv_bfloat162(h0, h1);
            *(__nv_bfloat162*)&Pl[(w16 + r0) * BP + col] = __nv_bfloat162(lo0, lo1);
            bsplit(p2, h0, lo0); bsplit(p3, h1, lo1);
            *(__nv_bfloat162*)&Ph[(w16 + r0 + 8) * BP + col] = __nv_bfloat162(h0, h1);
            *(__nv_bfloat162*)&Pl[(w16 + r0 + 8) * BP + col] = __nv_bfloat162(lo0, lo1);
        }
        l0s = l0s * al0 + ls0;
        l1s = l1s * al1 + ls1;

#pragma unroll
        for (int nt = 0; nt < 8; ++nt) {
            accO[nt][0] *= al0; accO[nt][1] *= al0;
            accO[nt][2] *= al1; accO[nt][3] *= al1;
        }
        __syncwarp();

#pragma unroll
        for (int kc = 0; kc < 4; ++kc) {
            const int kk = kc * 16 + 2 * q4;
            uint32_t ph[4], pl[4];
            ph[0] = *(const uint32_t*)&Ph[(w16 + r0    ) * BP + kk    ];
            ph[1] = *(const uint32_t*)&Ph[(w16 + r0 + 8) * BP + kk    ];
            ph[2] = *(const uint32_t*)&Ph[(w16 + r0    ) * BP + kk + 8];
            ph[3] = *(const uint32_t*)&Ph[(w16 + r0 + 8) * BP + kk + 8];
            pl[0] = *(const uint32_t*)&Pl[(w16 + r0    ) * BP + kk    ];
            pl[1] = *(const uint32_t*)&Pl[(w16 + r0 + 8) * BP + kk    ];
            pl[2] = *(const uint32_t*)&Pl[(w16 + r0    ) * BP + kk + 8];
            pl[3] = *(const uint32_t*)&Pl[(w16 + r0 + 8) * BP + kk + 8];
#pragma unroll
            for (int nt = 0; nt < 8; ++nt) {
                const int rb = (nt * 8 + r0) * BP;
                uint32_t vh[2], vl[2];
                vh[0] = *(const uint32_t*)&Vth[rb + kk    ];
                vh[1] = *(const uint32_t*)&Vth[rb + kk + 8];
                vl[0] = *(const uint32_t*)&Vtl[rb + kk    ];
                vl[1] = *(const uint32_t*)&Vtl[rb + kk + 8];
                mma16b(accO[nt], ph, vh);
                mma16b(accO[nt], ph, vl);
                mma16b(accO[nt], pl, vh);
            }
        }
    }

    l0s += __shfl_xor_sync(0xffffffff, l0s, 1);
    l0s += __shfl_xor_sync(0xffffffff, l0s, 2);
    l1s += __shfl_xor_sync(0xffffffff, l1s, 1);
    l1s += __shfl_xor_sync(0xffffffff, l1s, 2);
    float inv0 = 1.f / l0s;
    float inv1 = 1.f / l1s;

    __half* ob0 = g_oh + (size_t)(b * SS + qrow0) * DIM + h * HD;
    __half* ob1 = g_oh + (size_t)(b * SS + qrow1) * DIM + h * HD;
#pragma unroll
    for (int nt = 0; nt < 8; ++nt) {
        int col = nt * 8 + q4 * 2;
        *(__half2*)&ob0[col] = __floats2half2_rn(accO[nt][0] * inv0, accO[nt][1] * inv0);
        *(__half2*)&ob1[col] = __floats2half2_rn(accO[nt][2] * inv1, accO[nt][3] * inv1);
    }
}

// ---------------------------------------------------------------------------
extern "C" void kernel_launch(void* const* d_in, const int* in_sizes, int n_in,
                              void* d_out, int out_size)
{
    const float* x    = (const float*)d_in[0];
    const float* fc   = (const float*)d_in[1];
    const float* fs   = (const float*)d_in[2];
    const float* wqkv = (const float*)d_in[3];
    const float* wo   = (const float*)d_in[4];
    float* out = (float*)d_out;

    float  *qkv;
    __half *oh, *xh, *wqkvh, *woh;
    cudaGetSymbolAddress((void**)&qkv,   g_qkv);
    cudaGetSymbolAddress((void**)&oh,    g_oh);
    cudaGetSymbolAddress((void**)&xh,    g_xh);
    cudaGetSymbolAddress((void**)&wqkvh, g_wqkvh);
    cudaGetSymbolAddress((void**)&woh,   g_woh);

    cudaFuncSetAttribute(f16_gemm, cudaFuncAttributeMaxDynamicSharedMemorySize,
                         GEMM_SMEM);
    cudaFuncSetAttribute(flash_bf16_gqa, cudaFuncAttributeMaxDynamicSharedMemorySize,
                         FLASH_SMEM);

    // 0) fp16 convert inputs
    {
        int n4;
        n4 = BB * SS * DIM / 4;
        to_f16<<<(n4 + 255) / 256, 256>>>(x, xh, n4);
        n4 = ASH * DIM / 4;
        to_f16<<<(n4 + 255) / 256, 256>>>(wqkv, wqkvh, n4);
        n4 = DIM * DIM / 4;
        to_f16<<<(n4 + 255) / 256, 256>>>(wo, woh, n4);
    }

    // 1) QKV projection  [fp16 TC + ldmatrix]
    f16_gemm<<<dim3(ASH / BN, (BB * SS) / BM), 256, GEMM_SMEM>>>(
        xh, wqkvh, qkv, BB * SS, ASH, DIM);

    // 2) RoPE
    int total = BB * SS * (NH + NKV) * HHALF;
    rope_kernel<<<(total + 255) / 256, 256>>>(fc, fs);

    // 3) causal flash attention  [bf16x3 TC, GQA-shared K/V]
    flash_bf16_gqa<<<dim3(SS / 64, NKV, BB), 512, FLASH_SMEM>>>();

    // 4) output projection  [fp16 TC + ldmatrix]
    f16_gemm<<<dim3(DIM / BN, (BB * SS) / BM), 256, GEMM_SMEM>>>(
        oh, woh, out, BB * SS, DIM, DIM);
}

// round 16
// speedup vs baseline: 6.5513x; 1.0294x over previous
#include <cuda_runtime.h>
#include <cuda_bf16.h>
#include <cuda_fp16.h>
#include <cstdint>

#define BB 4
#define SS 1024
#define DIM 2048
#define NH 32
#define NKV 8
#define HD 64
#define QPK 4
#define ASH 3072
#define HHALF 32

// Scratch (device globals — allocation-free per harness rules)
__device__ float  g_qkv[BB * SS * ASH];    // qkv projection (f32, rope+flash input)
__device__ __half g_oh[BB * SS * DIM];     // attention out (fp16, WO gemm A operand)
__device__ __half g_xh[BB * SS * DIM];     // fp16 x
__device__ __half g_wqkvh[ASH * DIM];      // fp16 wqkv
__device__ __half g_woh[DIM * DIM];        // fp16 wo

__device__ __forceinline__ void mma16h(float* c, const uint32_t* a, const uint32_t* b) {
    asm volatile(
        "mma.sync.aligned.m16n8k16.row.col.f32.f16.f16.f32 "
        "{%0,%1,%2,%3}, {%4,%5,%6,%7}, {%8,%9}, {%0,%1,%2,%3};\n"
        : "+f"(c[0]), "+f"(c[1]), "+f"(c[2]), "+f"(c[3])
        : "r"(a[0]), "r"(a[1]), "r"(a[2]), "r"(a[3]), "r"(b[0]), "r"(b[1]));
}

__device__ __forceinline__ void ldsm_x4(uint32_t* r, uint32_t addr) {
    asm volatile("ldmatrix.sync.aligned.m8n8.x4.shared.b16 {%0,%1,%2,%3}, [%4];"
                 : "=r"(r[0]), "=r"(r[1]), "=r"(r[2]), "=r"(r[3]) : "r"(addr));
}

// ---------------------------------------------------------------------------
// Prepass: f32 -> f16 convert-copy
// ---------------------------------------------------------------------------
__global__ void to_f16(const float* __restrict__ in, __half* __restrict__ out, int n4)
{
    int i = blockIdx.x * blockDim.x + threadIdx.x;
    if (i >= n4) return;
    float4 v = ((const float4*)in)[i];
    ((__half2*)out)[2 * i]     = __floats2half2_rn(v.x, v.y);
    ((__half2*)out)[2 * i + 1] = __floats2half2_rn(v.z, v.w);
}

// ---------------------------------------------------------------------------
// FP16 TC GEMM (f32 accumulate): C[M,N] = A[M,K] * B[N,K]^T  (R12, at ceiling)
// ---------------------------------------------------------------------------
#define BM 128
#define BN 128
#define BKH 32
#define HPAD 40
#define GSTAGE 3
#define GEMM_SMEM (GSTAGE * (BM + BN) * HPAD * 2)   // 61,440 B

__device__ __forceinline__ void cp16(void* smem, const void* gmem) {
    uint32_t sa = (uint32_t)__cvta_generic_to_shared(smem);
    asm volatile("cp.async.cg.shared.global [%0], [%1], 16;\n" :: "r"(sa), "l"(gmem));
}

__global__ __launch_bounds__(256) void f16_gemm(
    const __half* __restrict__ A, const __half* __restrict__ Bm,
    float* __restrict__ C, int M, int N, int K)
{
    extern __shared__ __half hsm[];

    const int tid  = threadIdx.x;
    const int lane = tid & 31;
    const int warp = tid >> 5;
    const int wm = (warp >> 2) * 64;
    const int wn = (warp & 3) * 32;
    const int m0 = blockIdx.y * BM;
    const int n0 = blockIdx.x * BN;

    float acc[4][4][4];
#pragma unroll
    for (int mt = 0; mt < 4; mt++)
#pragma unroll
        for (int nt = 0; nt < 4; nt++)
#pragma unroll
            for (int r = 0; r < 4; r++) acc[mt][nt][r] = 0.f;

    const int ntiles = K / BKH;

    auto load_stage = [&](int s, int k0) {
        __half* as = hsm + s * (BM + BN) * HPAD;
        __half* bs = as + BM * HPAD;
#pragma unroll
        for (int it = 0; it < 2; ++it) {
            int f = tid + it * 256;
            int row = f >> 2, ch = (f & 3) * 8;
            cp16(as + row * HPAD + ch, A  + (size_t)(m0 + row) * K + k0 + ch);
            cp16(bs + row * HPAD + ch, Bm + (size_t)(n0 + row) * K + k0 + ch);
        }
        asm volatile("cp.async.commit_group;\n");
    };

    load_stage(0, 0);
    load_stage(1, BKH);

    const int l8 = lane & 7;
    const int a_row = ((lane >> 3) & 1) * 8 + l8;
    const int a_k   = (lane >> 4) * 8;
    const int b_row = (lane >> 4) * 8 + l8;
    const int b_k   = ((lane >> 3) & 1) * 8;

    const uint32_t smem0 = (uint32_t)__cvta_generic_to_shared(hsm);

    for (int kt = 0; kt < ntiles; ++kt) {
        if (kt + 1 < ntiles) asm volatile("cp.async.wait_group 1;\n");
        else                 asm volatile("cp.async.wait_group 0;\n");
        __syncthreads();

        if (kt + 2 < ntiles) load_stage((kt + 2) % GSTAGE, (kt + 2) * BKH);

        const uint32_t as = smem0 + (kt % GSTAGE) * (BM + BN) * HPAD * 2;
        const uint32_t bs = as + BM * HPAD * 2;
        const uint32_t abase = as + ((wm + a_row) * HPAD + a_k) * 2;
        const uint32_t bbase = bs + ((wn + b_row) * HPAD + b_k) * 2;

#pragma unroll
        for (int ks = 0; ks < BKH; ks += 16) {
            uint32_t af[4][4], bf[2][4];
#pragma unroll
            for (int mt = 0; mt < 4; mt++)
                ldsm_x4(af[mt], abase + (mt * 16 * HPAD + ks) * 2);
#pragma unroll
            for (int p = 0; p < 2; p++)
                ldsm_x4(bf[p], bbase + (p * 16 * HPAD + ks) * 2);
#pragma unroll
            for (int mt = 0; mt < 4; mt++)
#pragma unroll
                for (int nt = 0; nt < 4; nt++)
                    mma16h(acc[mt][nt], af[mt], &bf[nt >> 1][(nt & 1) * 2]);
        }
        __syncthreads();
    }

#pragma unroll
    for (int mt = 0; mt < 4; mt++) {
#pragma unroll
        for (int nt = 0; nt < 4; nt++) {
            int row = m0 + wm + mt * 16 + (lane >> 2);
            int col = n0 + wn + nt * 8 + 2 * (lane & 3);
            *(float2*)&C[(size_t)row * N + col] =
                make_float2(acc[mt][nt][0], acc[mt][nt][1]);
            *(float2*)&C[(size_t)(row + 8) * N + col] =
                make_float2(acc[mt][nt][2], acc[mt][nt][3]);
        }
    }
}

// ---------------------------------------------------------------------------
// RoPE on Q + K (f32, in-place on g_qkv)
// ---------------------------------------------------------------------------
__global__ void rope_kernel(const float* __restrict__ cosf,
                            const float* __restrict__ sinf)
{
    const int total = BB * SS * (NH + NKV) * HHALF;
    int idx = blockIdx.x * blockDim.x + threadIdx.x;
    if (idx >= total) return;

    int pair = idx % HHALF;
    int tmp  = idx / HHALF;
    int h    = tmp % (NH + NKV);
    tmp     /= (NH + NKV);
    int s    = tmp % SS;
    int b    = tmp / SS;

    int a;
    if (h < NH) a = (h / QPK) * ((QPK + 2) * HD) + (h % QPK) * HD;
    else        a = (h - NH) * ((QPK + 2) * HD) + QPK * HD;

    float* p = g_qkv + (size_t)(b * SS + s) * ASH + a + 2 * pair;
    float c  = cosf[s * HHALF + pair];
    float sn = sinf[s * HHALF + pair];
    float xr = p[0], xi = p[1];
    p[0] = xr * c - xi * sn;
    p[1] = xr * sn + xi * c;
}

// ---------------------------------------------------------------------------
// Flash attention, fp16 double-split (fp16x3: 22-bit effective mantissa),
// GQA-shared K/V, ldmatrix fragment loads, heavy-tiles-first scheduling.
// ---------------------------------------------------------------------------
#define BP 72
#define TS (64 * BP)
#define FLASH_SMEM (20 * TS * 2)   // 184,320 B

__device__ __forceinline__ void hsplit(float f, __half& hi, __half& lo) {
    hi = __float2half_rn(f);
    lo = __float2half_rn(f - __half2float(hi));
}

__global__ __launch_bounds__(512) void flash_f16_gqa()
{
    extern __shared__ __half smh[];
    __half* Kh     = smh;
    __half* Kl     = Kh  + TS;
    __half* Vth    = Kl  + TS;       // transposed: rows=d, cols=key
    __half* Vtl    = Vth + TS;
    __half* Qh_all = Vtl + TS;
    __half* Ql_all = Qh_all + 4 * TS;
    __half* Ph_all = Ql_all + 4 * TS;
    __half* Pl_all = Ph_all + 4 * TS;

    const int tid  = threadIdx.x;
    const int lane = tid & 31;
    const int warp = tid >> 5;
    const int qb = (SS / 64 - 1) - blockIdx.x;   // heavy CTAs first
    const int kv = blockIdx.y;
    const int b  = blockIdx.z;

    const int hg = warp >> 2;
    const int h  = kv * 4 + hg;
    const int koff = kv * 384 + 256;
    const int voff = kv * 384 + 320;

    __half* Qh = Qh_all + hg * TS;
    __half* Ql = Ql_all + hg * TS;
    __half* Ph = Ph_all + hg * TS;
    __half* Pl = Pl_all + hg * TS;

    // ---- load + split all 4 heads' Q tiles ----
#pragma unroll
    for (int it = 0; it < 8; ++it) {
        int f = tid + it * 512;
        int head = f >> 10;
        int rem  = f & 1023;
        int row  = rem >> 4, c4 = rem & 15;
        const float* src = g_qkv + (size_t)(b * SS + qb * 64 + row) * ASH
                         + kv * 384 + head * 64 + c4 * 4;
        float4 v = *(const float4*)src;
        __half h0, l0, h1, l1, h2, l2, h3, l3;
        hsplit(v.x, h0, l0); hsplit(v.y, h1, l1);
        hsplit(v.z, h2, l2); hsplit(v.w, h3, l3);
        int o = head * TS + row * BP + c4 * 4;
        Qh_all[o] = h0; Qh_all[o+1] = h1; Qh_all[o+2] = h2; Qh_all[o+3] = h3;
        Ql_all[o] = l0; Ql_all[o+1] = l1; Ql_all[o+2] = l2; Ql_all[o+3] = l3;
    }

    const int r0  = lane >> 2;
    const int q4  = lane & 3;
    const int w16 = (warp & 3) * 16;
    const int qrow0 = qb * 64 + w16 + r0;
    const int qrow1 = qrow0 + 8;
    const float scale = 0.125f;

    // ldmatrix lane mappings (same as f16_gemm, verified)
    const int l8 = lane & 7;
    const int a_row = ((lane >> 3) & 1) * 8 + l8;
    const int a_k   = (lane >> 4) * 8;
    const int b_row = (lane >> 4) * 8 + l8;
    const int b_k   = ((lane >> 3) & 1) * 8;

    const uint32_t qbh = (uint32_t)__cvta_generic_to_shared(&Qh[(w16 + a_row) * BP + a_k]);
    const uint32_t qbl = (uint32_t)__cvta_generic_to_shared(&Ql[(w16 + a_row) * BP + a_k]);
    const uint32_t pbh = (uint32_t)__cvta_generic_to_shared(&Ph[(w16 + a_row) * BP + a_k]);
    const uint32_t pbl = (uint32_t)__cvta_generic_to_shared(&Pl[(w16 + a_row) * BP + a_k]);
    const uint32_t kbh = (uint32_t)__cvta_generic_to_shared(&Kh[b_row * BP + b_k]);
    const uint32_t kbl = (uint32_t)__cvta_generic_to_shared(&Kl[b_row * BP + b_k]);
    const uint32_t vbh = (uint32_t)__cvta_generic_to_shared(&Vth[b_row * BP + b_k]);
    const uint32_t vbl = (uint32_t)__cvta_generic_to_shared(&Vtl[b_row * BP + b_k]);

    float accO[8][4];
#pragma unroll
    for (int nt = 0; nt < 8; nt++)
#pragma unroll
        for (int r = 0; r < 4; r++) accO[nt][r] = 0.f;

    float mr0 = -1e30f, mr1 = -1e30f;
    float l0s = 0.f, l1s = 0.f;

    for (int kb = 0; kb <= qb; ++kb) {
        __syncthreads();
        const float* kvb = g_qkv + (size_t)(b * SS + kb * 64) * ASH;
#pragma unroll
        for (int it = 0; it < 2; ++it) {
            int f = tid + it * 512;
            int row = f >> 4, c4 = f & 15;
            float4 kk = *(const float4*)(kvb + (size_t)row * ASH + koff + c4 * 4);
            float4 vv = *(const float4*)(kvb + (size_t)row * ASH + voff + c4 * 4);
            __half h0, lo0, h1, lo1, h2, lo2, h3, lo3;
            hsplit(kk.x, h0, lo0); hsplit(kk.y, h1, lo1);
            hsplit(kk.z, h2, lo2); hsplit(kk.w, h3, lo3);
            int o = row * BP + c4 * 4;
            Kh[o] = h0;  Kh[o+1] = h1;  Kh[o+2] = h2;  Kh[o+3] = h3;
            Kl[o] = lo0; Kl[o+1] = lo1; Kl[o+2] = lo2; Kl[o+3] = lo3;
            hsplit(vv.x, h0, lo0); hsplit(vv.y, h1, lo1);
            hsplit(vv.z, h2, lo2); hsplit(vv.w, h3, lo3);
            int d0 = c4 * 4;
            Vth[(d0    ) * BP + row] = h0;  Vtl[(d0    ) * BP + row] = lo0;
            Vth[(d0 + 1) * BP + row] = h1;  Vtl[(d0 + 1) * BP + row] = lo1;
            Vth[(d0 + 2) * BP + row] = h2;  Vtl[(d0 + 2) * BP + row] = lo2;
            Vth[(d0 + 3) * BP + row] = h3;  Vtl[(d0 + 3) * BP + row] = lo3;
        }
        __syncthreads();

        // ---- scores: S = Q @ K^T  (fp16x3, ldmatrix frags) ----
        float accS[8][4];
#pragma unroll
        for (int nt = 0; nt < 8; nt++)
#pragma unroll
            for (int r = 0; r < 4; r++) accS[nt][r] = 0.f;

#pragma unroll
        for (int kc = 0; kc < 4; ++kc) {
            uint32_t qh4[4], ql4[4];
            ldsm_x4(qh4, qbh + kc * 32);
            ldsm_x4(ql4, qbl + kc * 32);
#pragma unroll
            for (int np = 0; np < 4; ++np) {
                uint32_t kh4[4], kl4[4];
                ldsm_x4(kh4, kbh + np * (16 * BP * 2) + kc * 32);
                ldsm_x4(kl4, kbl + np * (16 * BP * 2) + kc * 32);
                mma16h(accS[2 * np],     qh4, &kh4[0]);
                mma16h(accS[2 * np],     qh4, &kl4[0]);
                mma16h(accS[2 * np],     ql4, &kh4[0]);
                mma16h(accS[2 * np + 1], qh4, &kh4[2]);
                mma16h(accS[2 * np + 1], qh4, &kl4[2]);
                mma16h(accS[2 * np + 1], ql4, &kh4[2]);
            }
        }

        // ---- mask + scale + online softmax ----
        float tmax0 = -1e30f, tmax1 = -1e30f;
#pragma unroll
        for (int nt = 0; nt < 8; ++nt) {
            int kc0 = kb * 64 + nt * 8 + q4 * 2;
#pragma unroll
            for (int c = 0; c < 2; ++c) {
                float s0 = accS[nt][c]     * scale;
                float s1 = accS[nt][c + 2] * scale;
                if (kc0 + c > qrow0) s0 = -1e30f;
                if (kc0 + c > qrow1) s1 = -1e30f;
                accS[nt][c]     = s0;
                accS[nt][c + 2] = s1;
                tmax0 = fmaxf(tmax0, s0);
                tmax1 = fmaxf(tmax1, s1);
            }
        }
        tmax0 = fmaxf(tmax0, __shfl_xor_sync(0xffffffff, tmax0, 1));
        tmax0 = fmaxf(tmax0, __shfl_xor_sync(0xffffffff, tmax0, 2));
        tmax1 = fmaxf(tmax1, __shfl_xor_sync(0xffffffff, tmax1, 1));
        tmax1 = fmaxf(tmax1, __shfl_xor_sync(0xffffffff, tmax1, 2));

        float mn0 = fmaxf(mr0, tmax0);
        float mn1 = fmaxf(mr1, tmax1);
        float al0 = __expf(mr0 - mn0);
        float al1 = __expf(mr1 - mn1);
        mr0 = mn0; mr1 = mn1;

        float ls0 = 0.f, ls1 = 0.f;
#pragma unroll
        for (int nt = 0; nt < 8; ++nt) {
            float p0 = __expf(accS[nt][0] - mn0);
            float p1 = __expf(accS[nt][1] - mn0);
            float p2 = __expf(accS[nt][2] - mn1);
            float p3 = __expf(accS[nt][3] - mn1);
            ls0 += p0 + p1;
            ls1 += p2 + p3;
            int col = nt * 8 + q4 * 2;
            __half h0, lo0, h1, lo1;
            hsplit(p0, h0, lo0); hsplit(p1, h1, lo1);
            *(__half2*)&Ph[(w16 + r0) * BP + col] = __halves2half2(h0, h1);
            *(__half2*)&Pl[(w16 + r0) * BP + col] = __halves2half2(lo0, lo1);
            hsplit(p2, h0, lo0); hsplit(p3, h1, lo1);
            *(__half2*)&Ph[(w16 + r0 + 8) * BP + col] = __halves2half2(h0, h1);
            *(__half2*)&Pl[(w16 + r0 + 8) * BP + col] = __halves2half2(lo0, lo1);
        }
        l0s = l0s * al0 + ls0;
        l1s = l1s * al1 + ls1;

#pragma unroll
        for (int nt = 0; nt < 8; ++nt) {
            accO[nt][0] *= al0; accO[nt][1] *= al0;
            accO[nt][2] *= al1; accO[nt][3] *= al1;
        }
        __syncwarp();

        // ---- PV: O += P @ V  (fp16x3, ldmatrix frags) ----
#pragma unroll
        for (int kc = 0; kc < 4; ++kc) {
            uint32_t ph4[4], pl4[4];
            ldsm_x4(ph4, pbh + kc * 32);
            ldsm_x4(pl4, pbl + kc * 32);
#pragma unroll
            for (int np = 0; np < 4; ++np) {
                uint32_t vh4[4], vl4[4];
                ldsm_x4(vh4, vbh + np * (16 * BP * 2) + kc * 32);
                ldsm_x4(vl4, vbl + np * (16 * BP * 2) + kc * 32);
                mma16h(accO[2 * np],     ph4, &vh4[0]);
                mma16h(accO[2 * np],     ph4, &vl4[0]);
                mma16h(accO[2 * np],     pl4, &vh4[0]);
                mma16h(accO[2 * np + 1], ph4, &vh4[2]);
                mma16h(accO[2 * np + 1], ph4, &vl4[2]);
                mma16h(accO[2 * np + 1], pl4, &vh4[2]);
            }
        }
    }

    // ---- finalize: write fp16 for WO gemm ----
    l0s += __shfl_xor_sync(0xffffffff, l0s, 1);
    l0s += __shfl_xor_sync(0xffffffff, l0s, 2);
    l1s += __shfl_xor_sync(0xffffffff, l1s, 1);
    l1s += __shfl_xor_sync(0xffffffff, l1s, 2);
    float inv0 = 1.f / l0s;
    float inv1 = 1.f / l1s;

    __half* ob0 = g_oh + (size_t)(b * SS + qrow0) * DIM + h * HD;
    __half* ob1 = g_oh + (size_t)(b * SS + qrow1) * DIM + h * HD;
#pragma unroll
    for (int nt = 0; nt < 8; ++nt) {
        int col = nt * 8 + q4 * 2;
        *(__half2*)&ob0[col] = __floats2half2_rn(accO[nt][0] * inv0, accO[nt][1] * inv0);
        *(__half2*)&ob1[col] = __floats2half2_rn(accO[nt][2] * inv1, accO[nt][3] * inv1);
    }
}

// ---------------------------------------------------------------------------
extern "C" void kernel_launch(void* const* d_in, const int* in_sizes, int n_in,
                              void* d_out, int out_size)
{
    const float* x    = (const float*)d_in[0];
    const float* fc   = (const float*)d_in[1];
    const float* fs   = (const float*)d_in[2];
    const float* wqkv = (const float*)d_in[3];
    const float* wo   = (const float*)d_in[4];
    float* out = (float*)d_out;

    float  *qkv;
    __half *oh, *xh, *wqkvh, *woh;
    cudaGetSymbolAddress((void**)&qkv,   g_qkv);
    cudaGetSymbolAddress((void**)&oh,    g_oh);
    cudaGetSymbolAddress((void**)&xh,    g_xh);
    cudaGetSymbolAddress((void**)&wqkvh, g_wqkvh);
    cudaGetSymbolAddress((void**)&woh,   g_woh);

    cudaFuncSetAttribute(f16_gemm, cudaFuncAttributeMaxDynamicSharedMemorySize,
                         GEMM_SMEM);
    cudaFuncSetAttribute(flash_f16_gqa, cudaFuncAttributeMaxDynamicSharedMemorySize,
                         FLASH_SMEM);

    // 0) fp16 convert inputs
    {
        int n4;
        n4 = BB * SS * DIM / 4;
        to_f16<<<(n4 + 255) / 256, 256>>>(x, xh, n4);
        n4 = ASH * DIM / 4;
        to_f16<<<(n4 + 255) / 256, 256>>>(wqkv, wqkvh, n4);
        n4 = DIM * DIM / 4;
        to_f16<<<(n4 + 255) / 256, 256>>>(wo, woh, n4);
    }

    // 1) QKV projection  [fp16 TC + ldmatrix]
    f16_gemm<<<dim3(ASH / BN, (BB * SS) / BM), 256, GEMM_SMEM>>>(
        xh, wqkvh, qkv, BB * SS, ASH, DIM);

    // 2) RoPE
    int total = BB * SS * (NH + NKV) * HHALF;
    rope_kernel<<<(total + 255) / 256, 256>>>(fc, fs);

    // 3) causal flash attention  [fp16x3 TC, GQA-shared K/V, ldmatrix]
    flash_f16_gqa<<<dim3(SS / 64, NKV, BB), 512, FLASH_SMEM>>>();

    // 4) output projection  [fp16 TC + ldmatrix]
    f16_gemm<<<dim3(DIM / BN, (BB * SS) / BM), 256, GEMM_SMEM>>>(
        oh, woh, out, BB * SS, DIM, DIM);
}

// round 17
// speedup vs baseline: 7.0336x; 1.0736x over previous
#include <cuda_runtime.h>
#include <cuda_fp16.h>
#include <cstdint>

#define BB 4
#define SS 1024
#define DIM 2048
#define NH 32
#define NKV 8
#define HD 64
#define QPK 4
#define ASH 3072
#define HHALF 32

// Scratch (device globals — allocation-free per harness rules)
__device__ float  g_qkv[BB * SS * ASH];    // qkv projection (f32, rope applied in epilogue)
__device__ __half g_oh[BB * SS * DIM];     // attention out (fp16, WO gemm A operand)
__device__ __half g_xh[BB * SS * DIM];     // fp16 x
__device__ __half g_wqkvh[ASH * DIM];      // fp16 wqkv
__device__ __half g_woh[DIM * DIM];        // fp16 wo

__device__ __forceinline__ void mma16h(float* c, const uint32_t* a, const uint32_t* b) {
    asm volatile(
        "mma.sync.aligned.m16n8k16.row.col.f32.f16.f16.f32 "
        "{%0,%1,%2,%3}, {%4,%5,%6,%7}, {%8,%9}, {%0,%1,%2,%3};\n"
        : "+f"(c[0]), "+f"(c[1]), "+f"(c[2]), "+f"(c[3])
        : "r"(a[0]), "r"(a[1]), "r"(a[2]), "r"(a[3]), "r"(b[0]), "r"(b[1]));
}

__device__ __forceinline__ void ldsm_x4(uint32_t* r, uint32_t addr) {
    asm volatile("ldmatrix.sync.aligned.m8n8.x4.shared.b16 {%0,%1,%2,%3}, [%4];"
                 : "=r"(r[0]), "=r"(r[1]), "=r"(r[2]), "=r"(r[3]) : "r"(addr));
}

// ---------------------------------------------------------------------------
// Prepass: f32 -> f16 convert-copy
// ---------------------------------------------------------------------------
__global__ void to_f16(const float* __restrict__ in, __half* __restrict__ out, int n4)
{
    int i = blockIdx.x * blockDim.x + threadIdx.x;
    if (i >= n4) return;
    float4 v = ((const float4*)in)[i];
    ((__half2*)out)[2 * i]     = __floats2half2_rn(v.x, v.y);
    ((__half2*)out)[2 * i + 1] = __floats2half2_rn(v.z, v.w);
}

// ---------------------------------------------------------------------------
// FP16 TC GEMM (f32 accumulate): C[M,N] = A[M,K] * B[N,K]^T, fp16 K-major.
// Optional fused RoPE in the epilogue (do_rope=1 for the QKV projection):
// c-fragment pair (col, col+1) is exactly one interleaved rope pair.
// ---------------------------------------------------------------------------
#define BM 128
#define BN 128
#define BKH 32
#define HPAD 40
#define GSTAGE 3
#define GEMM_SMEM (GSTAGE * (BM + BN) * HPAD * 2)   // 61,440 B

__device__ __forceinline__ void cp16(void* smem, const void* gmem) {
    uint32_t sa = (uint32_t)__cvta_generic_to_shared(smem);
    asm volatile("cp.async.cg.shared.global [%0], [%1], 16;\n" :: "r"(sa), "l"(gmem));
}

__global__ __launch_bounds__(256) void f16_gemm(
    const __half* __restrict__ A, const __half* __restrict__ Bm,
    float* __restrict__ C, int M, int N, int K,
    int do_rope, const float* __restrict__ cosf_, const float* __restrict__ sinf_)
{
    extern __shared__ __half hsm[];

    const int tid  = threadIdx.x;
    const int lane = tid & 31;
    const int warp = tid >> 5;
    const int wm = (warp >> 2) * 64;
    const int wn = (warp & 3) * 32;
    const int m0 = blockIdx.y * BM;
    const int n0 = blockIdx.x * BN;

    float acc[4][4][4];
#pragma unroll
    for (int mt = 0; mt < 4; mt++)
#pragma unroll
        for (int nt = 0; nt < 4; nt++)
#pragma unroll
            for (int r = 0; r < 4; r++) acc[mt][nt][r] = 0.f;

    const int ntiles = K / BKH;

    auto load_stage = [&](int s, int k0) {
        __half* as = hsm + s * (BM + BN) * HPAD;
        __half* bs = as + BM * HPAD;
#pragma unroll
        for (int it = 0; it < 2; ++it) {
            int f = tid + it * 256;
            int row = f >> 2, ch = (f & 3) * 8;
            cp16(as + row * HPAD + ch, A  + (size_t)(m0 + row) * K + k0 + ch);
            cp16(bs + row * HPAD + ch, Bm + (size_t)(n0 + row) * K + k0 + ch);
        }
        asm volatile("cp.async.commit_group;\n");
    };

    load_stage(0, 0);
    load_stage(1, BKH);

    const int l8 = lane & 7;
    const int a_row = ((lane >> 3) & 1) * 8 + l8;
    const int a_k   = (lane >> 4) * 8;
    const int b_row = (lane >> 4) * 8 + l8;
    const int b_k   = ((lane >> 3) & 1) * 8;

    const uint32_t smem0 = (uint32_t)__cvta_generic_to_shared(hsm);

    for (int kt = 0; kt < ntiles; ++kt) {
        if (kt + 1 < ntiles) asm volatile("cp.async.wait_group 1;\n");
        else                 asm volatile("cp.async.wait_group 0;\n");
        __syncthreads();

        if (kt + 2 < ntiles) load_stage((kt + 2) % GSTAGE, (kt + 2) * BKH);

        const uint32_t as = smem0 + (kt % GSTAGE) * (BM + BN) * HPAD * 2;
        const uint32_t bs = as + BM * HPAD * 2;
        const uint32_t abase = as + ((wm + a_row) * HPAD + a_k) * 2;
        const uint32_t bbase = bs + ((wn + b_row) * HPAD + b_k) * 2;

#pragma unroll
        for (int ks = 0; ks < BKH; ks += 16) {
            uint32_t af[4][4], bf[2][4];
#pragma unroll
            for (int mt = 0; mt < 4; mt++)
                ldsm_x4(af[mt], abase + (mt * 16 * HPAD + ks) * 2);
#pragma unroll
            for (int p = 0; p < 2; p++)
                ldsm_x4(bf[p], bbase + (p * 16 * HPAD + ks) * 2);
#pragma unroll
            for (int mt = 0; mt < 4; mt++)
#pragma unroll
                for (int nt = 0; nt < 4; nt++)
                    mma16h(acc[mt][nt], af[mt], &bf[nt >> 1][(nt & 1) * 2]);
        }
        __syncthreads();
    }

#pragma unroll
    for (int mt = 0; mt < 4; mt++) {
#pragma unroll
        for (int nt = 0; nt < 4; nt++) {
            int row = m0 + wm + mt * 16 + (lane >> 2);
            int col = n0 + wn + nt * 8 + 2 * (lane & 3);
            float v0 = acc[mt][nt][0], v1 = acc[mt][nt][1];
            float v2 = acc[mt][nt][2], v3 = acc[mt][nt][3];
            if (do_rope) {
                int r = col % 384;
                if (r < 320) {                     // q (r<256) or k (256..319)
                    int pair = (col & 63) >> 1;
                    int s0 = row & (SS - 1);
                    float c0 = cosf_[s0 * HHALF + pair];
                    float n0_ = sinf_[s0 * HHALF + pair];
                    float t0 = v0 * c0 - v1 * n0_;
                    v1 = v0 * n0_ + v1 * c0;  v0 = t0;
                    int s1 = (row + 8) & (SS - 1);
                    float c1 = cosf_[s1 * HHALF + pair];
                    float n1_ = sinf_[s1 * HHALF + pair];
                    float t2 = v2 * c1 - v3 * n1_;
                    v3 = v2 * n1_ + v3 * c1;  v2 = t2;
                }
            }
            *(float2*)&C[(size_t)row * N + col]       = make_float2(v0, v1);
            *(float2*)&C[(size_t)(row + 8) * N + col] = make_float2(v2, v3);
        }
    }
}

// ---------------------------------------------------------------------------
// Flash attention: 2-term fp16 splits (K and V carry hi+lo; Q and P hi-only).
// S ~= qh*kh + qh*kl  (err ~2.4e-4*|s|, |s|~O(1));  O ~= ph*vh + ph*vl.
// GQA-shared K/V, ldmatrix frags, heavy-tiles-first. 12 smem tiles = 110 KB.
// ---------------------------------------------------------------------------
#define BP 72
#define TS (64 * BP)
#define FLASH_SMEM (12 * TS * 2)   // 110,592 B

__device__ __forceinline__ void hsplit(float f, __half& hi, __half& lo) {
    hi = __float2half_rn(f);
    lo = __float2half_rn(f - __half2float(hi));
}

__global__ __launch_bounds__(512) void flash_f16_gqa()
{
    extern __shared__ __half smh[];
    __half* Kh     = smh;
    __half* Kl     = Kh  + TS;
    __half* Vth    = Kl  + TS;       // transposed: rows=d, cols=key
    __half* Vtl    = Vth + TS;
    __half* Qh_all = Vtl + TS;       // 4 heads, hi only
    __half* Ph_all = Qh_all + 4 * TS;

    const int tid  = threadIdx.x;
    const int lane = tid & 31;
    const int warp = tid >> 5;
    const int qb = (SS / 64 - 1) - blockIdx.x;   // heavy CTAs first
    const int kv = blockIdx.y;
    const int b  = blockIdx.z;

    const int hg = warp >> 2;
    const int h  = kv * 4 + hg;
    const int koff = kv * 384 + 256;
    const int voff = kv * 384 + 320;

    __half* Qh = Qh_all + hg * TS;
    __half* Ph = Ph_all + hg * TS;

    // ---- load all 4 heads' Q tiles (hi only) ----
#pragma unroll
    for (int it = 0; it < 8; ++it) {
        int f = tid + it * 512;
        int head = f >> 10;
        int rem  = f & 1023;
        int row  = rem >> 4, c4 = rem & 15;
        const float* src = g_qkv + (size_t)(b * SS + qb * 64 + row) * ASH
                         + kv * 384 + head * 64 + c4 * 4;
        float4 v = *(const float4*)src;
        int o = head * TS + row * BP + c4 * 4;
        *(__half2*)&Qh_all[o]     = __floats2half2_rn(v.x, v.y);
        *(__half2*)&Qh_all[o + 2] = __floats2half2_rn(v.z, v.w);
    }

    const int r0  = lane >> 2;
    const int q4  = lane & 3;
    const int w16 = (warp & 3) * 16;
    const int qrow0 = qb * 64 + w16 + r0;
    const int qrow1 = qrow0 + 8;
    const float scale = 0.125f;

    // ldmatrix lane mappings
    const int l8 = lane & 7;
    const int a_row = ((lane >> 3) & 1) * 8 + l8;
    const int a_k   = (lane >> 4) * 8;
    const int b_row = (lane >> 4) * 8 + l8;
    const int b_k   = ((lane >> 3) & 1) * 8;

    const uint32_t qbh = (uint32_t)__cvta_generic_to_shared(&Qh[(w16 + a_row) * BP + a_k]);
    const uint32_t pbh = (uint32_t)__cvta_generic_to_shared(&Ph[(w16 + a_row) * BP + a_k]);
    const uint32_t kbh = (uint32_t)__cvta_generic_to_shared(&Kh[b_row * BP + b_k]);
    const uint32_t kbl = (uint32_t)__cvta_generic_to_shared(&Kl[b_row * BP + b_k]);
    const uint32_t vbh = (uint32_t)__cvta_generic_to_shared(&Vth[b_row * BP + b_k]);
    const uint32_t vbl = (uint32_t)__cvta_generic_to_shared(&Vtl[b_row * BP + b_k]);

    float accO[8][4];
#pragma unroll
    for (int nt = 0; nt < 8; nt++)
#pragma unroll
        for (int r = 0; r < 4; r++) accO[nt][r] = 0.f;

    float mr0 = -1e30f, mr1 = -1e30f;
    float l0s = 0.f, l1s = 0.f;

    for (int kb = 0; kb <= qb; ++kb) {
        __syncthreads();
        const float* kvb = g_qkv + (size_t)(b * SS + kb * 64) * ASH;
#pragma unroll
        for (int it = 0; it < 2; ++it) {
            int f = tid + it * 512;
            int row = f >> 4, c4 = f & 15;
            float4 kk = *(const float4*)(kvb + (size_t)row * ASH + koff + c4 * 4);
            float4 vv = *(const float4*)(kvb + (size_t)row * ASH + voff + c4 * 4);
            __half h0, lo0, h1, lo1, h2, lo2, h3, lo3;
            hsplit(kk.x, h0, lo0); hsplit(kk.y, h1, lo1);
            hsplit(kk.z, h2, lo2); hsplit(kk.w, h3, lo3);
            int o = row * BP + c4 * 4;
            Kh[o] = h0;  Kh[o+1] = h1;  Kh[o+2] = h2;  Kh[o+3] = h3;
            Kl[o] = lo0; Kl[o+1] = lo1; Kl[o+2] = lo2; Kl[o+3] = lo3;
            hsplit(vv.x, h0, lo0); hsplit(vv.y, h1, lo1);
            hsplit(vv.z, h2, lo2); hsplit(vv.w, h3, lo3);
            int d0 = c4 * 4;
            Vth[(d0    ) * BP + row] = h0;  Vtl[(d0    ) * BP + row] = lo0;
            Vth[(d0 + 1) * BP + row] = h1;  Vtl[(d0 + 1) * BP + row] = lo1;
            Vth[(d0 + 2) * BP + row] = h2;  Vtl[(d0 + 2) * BP + row] = lo2;
            Vth[(d0 + 3) * BP + row] = h3;  Vtl[(d0 + 3) * BP + row] = lo3;
        }
        __syncthreads();

        // ---- scores: S = Qh @ (Kh + Kl)^T ----
        float accS[8][4];
#pragma unroll
        for (int nt = 0; nt < 8; nt++)
#pragma unroll
            for (int r = 0; r < 4; r++) accS[nt][r] = 0.f;

#pragma unroll
        for (int kc = 0; kc < 4; ++kc) {
            uint32_t qh4[4];
            ldsm_x4(qh4, qbh + kc * 32);
#pragma unroll
            for (int np = 0; np < 4; ++np) {
                uint32_t kh4[4], kl4[4];
                ldsm_x4(kh4, kbh + np * (16 * BP * 2) + kc * 32);
                ldsm_x4(kl4, kbl + np * (16 * BP * 2) + kc * 32);
                mma16h(accS[2 * np],     qh4, &kh4[0]);
                mma16h(accS[2 * np],     qh4, &kl4[0]);
                mma16h(accS[2 * np + 1], qh4, &kh4[2]);
                mma16h(accS[2 * np + 1], qh4, &kl4[2]);
            }
        }

        // ---- mask + scale + online softmax ----
        float tmax0 = -1e30f, tmax1 = -1e30f;
#pragma unroll
        for (int nt = 0; nt < 8; ++nt) {
            int kc0 = kb * 64 + nt * 8 + q4 * 2;
#pragma unroll
            for (int c = 0; c < 2; ++c) {
                float s0 = accS[nt][c]     * scale;
                float s1 = accS[nt][c + 2] * scale;
                if (kc0 + c > qrow0) s0 = -1e30f;
                if (kc0 + c > qrow1) s1 = -1e30f;
                accS[nt][c]     = s0;
                accS[nt][c + 2] = s1;
                tmax0 = fmaxf(tmax0, s0);
                tmax1 = fmaxf(tmax1, s1);
            }
        }
        tmax0 = fmaxf(tmax0, __shfl_xor_sync(0xffffffff, tmax0, 1));
        tmax0 = fmaxf(tmax0, __shfl_xor_sync(0xffffffff, tmax0, 2));
        tmax1 = fmaxf(tmax1, __shfl_xor_sync(0xffffffff, tmax1, 1));
        tmax1 = fmaxf(tmax1, __shfl_xor_sync(0xffffffff, tmax1, 2));

        float mn0 = fmaxf(mr0, tmax0);
        float mn1 = fmaxf(mr1, tmax1);
        float al0 = __expf(mr0 - mn0);
        float al1 = __expf(mr1 - mn1);
        mr0 = mn0; mr1 = mn1;

        float ls0 = 0.f, ls1 = 0.f;
#pragma unroll
        for (int nt = 0; nt < 8; ++nt) {
            float p0 = __expf(accS[nt][0] - mn0);
            float p1 = __expf(accS[nt][1] - mn0);
            float p2 = __expf(accS[nt][2] - mn1);
            float p3 = __expf(accS[nt][3] - mn1);
            ls0 += p0 + p1;
            ls1 += p2 + p3;
            int col = nt * 8 + q4 * 2;
            *(__half2*)&Ph[(w16 + r0    ) * BP + col] = __floats2half2_rn(p0, p1);
            *(__half2*)&Ph[(w16 + r0 + 8) * BP + col] = __floats2half2_rn(p2, p3);
        }
        l0s = l0s * al0 + ls0;
        l1s = l1s * al1 + ls1;

#pragma unroll
        for (int nt = 0; nt < 8; ++nt) {
            accO[nt][0] *= al0; accO[nt][1] *= al0;
            accO[nt][2] *= al1; accO[nt][3] *= al1;
        }
        __syncwarp();

        // ---- PV: O += Ph @ (Vh + Vl) ----
#pragma unroll
        for (int kc = 0; kc < 4; ++kc) {
            uint32_t ph4[4];
            ldsm_x4(ph4, pbh + kc * 32);
#pragma unroll
            for (int np = 0; np < 4; ++np) {
                uint32_t vh4[4], vl4[4];
                ldsm_x4(vh4, vbh + np * (16 * BP * 2) + kc * 32);
                ldsm_x4(vl4, vbl + np * (16 * BP * 2) + kc * 32);
                mma16h(accO[2 * np],     ph4, &vh4[0]);
                mma16h(accO[2 * np],     ph4, &vl4[0]);
                mma16h(accO[2 * np + 1], ph4, &vh4[2]);
                mma16h(accO[2 * np + 1], ph4, &vl4[2]);
            }
        }
    }

    // ---- finalize: write fp16 for WO gemm ----
    l0s += __shfl_xor_sync(0xffffffff, l0s, 1);
    l0s += __shfl_xor_sync(0xffffffff, l0s, 2);
    l1s += __shfl_xor_sync(0xffffffff, l1s, 1);
    l1s += __shfl_xor_sync(0xffffffff, l1s, 2);
    float inv0 = 1.f / l0s;
    float inv1 = 1.f / l1s;

    __half* ob0 = g_oh + (size_t)(b * SS + qrow0) * DIM + h * HD;
    __half* ob1 = g_oh + (size_t)(b * SS + qrow1) * DIM + h * HD;
#pragma unroll
    for (int nt = 0; nt < 8; ++nt) {
        int col = nt * 8 + q4 * 2;
        *(__half2*)&ob0[col] = __floats2half2_rn(accO[nt][0] * inv0, accO[nt][1] * inv0);
        *(__half2*)&ob1[col] = __floats2half2_rn(accO[nt][2] * inv1, accO[nt][3] * inv1);
    }
}

// ---------------------------------------------------------------------------
extern "C" void kernel_launch(void* const* d_in, const int* in_sizes, int n_in,
                              void* d_out, int out_size)
{
    const float* x    = (const float*)d_in[0];
    const float* fc   = (const float*)d_in[1];
    const float* fs   = (const float*)d_in[2];
    const float* wqkv = (const float*)d_in[3];
    const float* wo   = (const float*)d_in[4];
    float* out = (float*)d_out;

    float  *qkv;
    __half *oh, *xh, *wqkvh, *woh;
    cudaGetSymbolAddress((void**)&qkv,   g_qkv);
    cudaGetSymbolAddress((void**)&oh,    g_oh);
    cudaGetSymbolAddress((void**)&xh,    g_xh);
    cudaGetSymbolAddress((void**)&wqkvh, g_wqkvh);
    cudaGetSymbolAddress((void**)&woh,   g_woh);

    cudaFuncSetAttribute(f16_gemm, cudaFuncAttributeMaxDynamicSharedMemorySize,
                         GEMM_SMEM);
    cudaFuncSetAttribute(flash_f16_gqa, cudaFuncAttributeMaxDynamicSharedMemorySize,
                         FLASH_SMEM);

    // 0) fp16 convert inputs
    {
        int n4;
        n4 = BB * SS * DIM / 4;
        to_f16<<<(n4 + 255) / 256, 256>>>(x, xh, n4);
        n4 = ASH * DIM / 4;
        to_f16<<<(n4 + 255) / 256, 256>>>(wqkv, wqkvh, n4);
        n4 = DIM * DIM / 4;
        to_f16<<<(n4 + 255) / 256, 256>>>(wo, woh, n4);
    }

    // 1) QKV projection + fused RoPE  [fp16 TC + ldmatrix]
    f16_gemm<<<dim3(ASH / BN, (BB * SS) / BM), 256, GEMM_SMEM>>>(
        xh, wqkvh, qkv, BB * SS, ASH, DIM, 1, fc, fs);

    // 2) causal flash attention  [fp16 2-term split TC, GQA-shared K/V]
    flash_f16_gqa<<<dim3(SS / 64, NKV, BB), 512, FLASH_SMEM>>>();

    // 3) output projection  [fp16 TC + ldmatrix]
    f16_gemm<<<dim3(DIM / BN, (BB * SS) / BM), 256, GEMM_SMEM>>>(
        oh, woh, out, BB * SS, DIM, DIM, 0, nullptr, nullptr);
}